// round 7
// baseline (speedup 1.0000x reference)
#include <cuda_runtime.h>
#include <math.h>

#define BB 4
#define HH 8
#define LL 1024
#define DD 32
#define DIMM 256
#define ATT_SCALE 0.0625f   // DIM^-0.5 = 1/16

#define M1 1048576
// scratch layout (floats)
#define OFF_XQ  (0*M1)
#define OFF_XK  (1*M1)
#define OFF_XV  (2*M1)
#define OFF_RV  (3*M1)
#define OFF_Q   (4*M1)
#define OFF_K   (5*M1)
#define OFF_VM  (6*M1)
#define OFF_VRM (7*M1)
#define OFF_PCOL (8*M1)                     // 8 segs x 32 bi x 1024 t
#define OFF_RMAX (8*M1 + 262144)            // 2 t-halves x 32768 rows

__device__ float g_scratch[8*M1 + 262144 + 65536];

// packed fp32x2 helpers (sm_100+)
#define FMA2(acc, a, b) \
    asm("fma.rn.f32x2 %0, %1, %2, %0;" : "+l"(acc) : "l"(a), "l"(b))
#define DUP2(dst, v) \
    asm("mov.b64 %0, {%1, %1};" : "=l"(dst) : "f"(v))
#define UNPACK2(lo, hi, v) \
    asm("mov.b64 {%0, %1}, %2;" : "=f"(lo), "=f"(hi) : "l"(v))

// ---------------------------------------------------------------------------
// K1: per-head projections  dst[b,h,t,d] = sum_dp src[b,t,h*32+dp] * W[dp,d]
// ---------------------------------------------------------------------------
__global__ __launch_bounds__(256) void proj_kernel(
    const float* __restrict__ x, const float* __restrict__ rx,
    const float* __restrict__ Wq, const float* __restrict__ Wk,
    const float* __restrict__ Wv, float* __restrict__ scratch)
{
    int tid = threadIdx.x;
    int which = blockIdx.y;
    const float* src = (which == 0 || which == 2) ? x : rx;
    const float* W = (which == 0) ? Wq : ((which == 1) ? Wk : Wv);
    float* dst = scratch + (size_t)which * M1;

    __shared__ float Ws[1024];
    __shared__ float Xs[8][32];
    for (int i = tid; i < 1024; i += 256) Ws[i] = W[i];

    int r = blockIdx.x * 8 + (tid >> 5);   // r = (b*8+h)*1024 + t
    int d = tid & 31;
    int b = r >> 13;
    int h = (r >> 10) & 7;
    int t = r & 1023;
    Xs[tid >> 5][d] = src[((size_t)(b * LL + t)) * DIMM + h * 32 + d];
    __syncthreads();

    float acc = 0.f;
    #pragma unroll
    for (int dp = 0; dp < 32; dp++) acc += Xs[tid >> 5][dp] * Ws[dp * 32 + d];
    dst[(size_t)r * 32 + d] = acc;
}

// ---------------------------------------------------------------------------
// K2: SPARSE binary gather-sum:  O[bh][l][d] = sum_{t: G[bh][l][t] > 0} X[bh][t][d]
// G values exactly 0.0/1.0 -> zero-skip is bit-exact.
// ---------------------------------------------------------------------------
__global__ __launch_bounds__(256) void spmm_binary(
    const float* __restrict__ G0, const float* __restrict__ X0, float* __restrict__ O0,
    const float* __restrict__ G1, const float* __restrict__ X1, float* __restrict__ O1)
{
    int lane = threadIdx.x & 31, w = threadIdx.x >> 5;
    int l = blockIdx.x * 8 + w;
    int bh = blockIdx.y;
    const float* G = (blockIdx.z ? G1 : G0) + (size_t)bh * (LL * LL) + (size_t)l * LL;
    const float* X = (blockIdx.z ? X1 : X0) + (size_t)bh * (LL * DD);
    float* O = (blockIdx.z ? O1 : O0) + (size_t)bh * (LL * DD);

    float acc0 = 0.f, acc1 = 0.f;
    for (int t0 = 0; t0 < LL; t0 += 128) {
        float4 g = *(const float4*)&G[t0 + lane * 4];
        #pragma unroll
        for (int c = 0; c < 4; c++) {
            float gv = (c == 0) ? g.x : (c == 1) ? g.y : (c == 2) ? g.z : g.w;
            unsigned m = __ballot_sync(0xffffffffu, gv > 0.f);
            while (m) {
                int j = __ffs(m) - 1; m &= m - 1;
                acc0 += X[(t0 + j * 4 + c) * DD + lane];
                if (m) {
                    j = __ffs(m) - 1; m &= m - 1;
                    acc1 += X[(t0 + j * 4 + c) * DD + lane];
                }
            }
        }
    }
    O[(size_t)l * DD + lane] = acc0 + acc1;
}

// ---------------------------------------------------------------------------
// K2c: DENSE per-(b,h) SGEMM (vr = Ar @ rv; Ar is dense).
// ---------------------------------------------------------------------------
__global__ __launch_bounds__(256) void gemm_dense(
    const float* __restrict__ Amat, const float* __restrict__ Bm,
    float* __restrict__ C, size_t c_b_stride, size_t c_h_stride, int c_row_stride)
{
    __shared__ float Ast[32][132];   // transposed A tile [k][row]
    __shared__ float Bs[1024];       // [k][d]

    int tid = threadIdx.x;
    int bh = blockIdx.y;
    const float* A  = Amat + (size_t)bh * (LL * LL);
    const float* Bb = Bm + (size_t)bh * (LL * DD);
    float* Cb = C + (size_t)(bh >> 3) * c_b_stride + (size_t)(bh & 7) * c_h_stride;
    int l0 = blockIdx.x * 128;

    int d = tid & 31, rg = tid >> 5;
    int lrow = tid >> 1, cseg = (tid & 1) * 16;

    unsigned long long acc2[8];
    #pragma unroll
    for (int j = 0; j < 8; j++) acc2[j] = 0ULL;

    float4 pa0, pa1, pa2, pa3, pb;
    {
        const float* p = A + (size_t)(l0 + lrow) * LL + cseg;
        pa0 = *(const float4*)(p);      pa1 = *(const float4*)(p + 4);
        pa2 = *(const float4*)(p + 8);  pa3 = *(const float4*)(p + 12);
        pb  = *(const float4*)(Bb + tid * 4);
    }

    for (int c = 0; c < 32; c++) {
        Ast[cseg+ 0][lrow]=pa0.x; Ast[cseg+ 1][lrow]=pa0.y;
        Ast[cseg+ 2][lrow]=pa0.z; Ast[cseg+ 3][lrow]=pa0.w;
        Ast[cseg+ 4][lrow]=pa1.x; Ast[cseg+ 5][lrow]=pa1.y;
        Ast[cseg+ 6][lrow]=pa1.z; Ast[cseg+ 7][lrow]=pa1.w;
        Ast[cseg+ 8][lrow]=pa2.x; Ast[cseg+ 9][lrow]=pa2.y;
        Ast[cseg+10][lrow]=pa2.z; Ast[cseg+11][lrow]=pa2.w;
        Ast[cseg+12][lrow]=pa3.x; Ast[cseg+13][lrow]=pa3.y;
        Ast[cseg+14][lrow]=pa3.z; Ast[cseg+15][lrow]=pa3.w;
        *(float4*)&Bs[tid * 4] = pb;
        __syncthreads();

        if (c < 31) {
            int k0 = (c + 1) * 32;
            const float* p = A + (size_t)(l0 + lrow) * LL + k0 + cseg;
            pa0 = *(const float4*)(p);      pa1 = *(const float4*)(p + 4);
            pa2 = *(const float4*)(p + 8);  pa3 = *(const float4*)(p + 12);
            pb  = *(const float4*)(Bb + (size_t)k0 * DD + tid * 4);
        }

        #pragma unroll
        for (int kk = 0; kk < 32; kk++) {
            float bv = Bs[kk * 32 + d];
            unsigned long long bvv;
            DUP2(bvv, bv);
            const ulonglong2* ap = (const ulonglong2*)&Ast[kk][rg * 16];
            ulonglong2 q0 = ap[0];
            ulonglong2 q1 = ap[1];
            ulonglong2 q2 = ap[2];
            ulonglong2 q3 = ap[3];
            FMA2(acc2[0], q0.x, bvv); FMA2(acc2[1], q0.y, bvv);
            FMA2(acc2[2], q1.x, bvv); FMA2(acc2[3], q1.y, bvv);
            FMA2(acc2[4], q2.x, bvv); FMA2(acc2[5], q2.y, bvv);
            FMA2(acc2[6], q3.x, bvv); FMA2(acc2[7], q3.y, bvv);
        }
        __syncthreads();
    }

    #pragma unroll
    for (int j = 0; j < 8; j++) {
        float lo, hi;
        UNPACK2(lo, hi, acc2[j]);
        Cb[(size_t)(l0 + rg * 16 + 2*j    ) * c_row_stride + d] = lo;
        Cb[(size_t)(l0 + rg * 16 + 2*j + 1) * c_row_stride + d] = hi;
    }
}

// ---------------------------------------------------------------------------
// K3: logits + leaky + R-mix + mask -> raw logits (or -inf) in M_out; partial
// row max per t-half to rmax_out. grid.z = t-half (512 t's each).
// ---------------------------------------------------------------------------
struct AttnSmem {
    float Qs[8][8][32];
    float Ss[2][8][8][32];
    float Ks[8][32][36];
    float Rs[64];
};

extern __shared__ unsigned char attn_smem_raw[];

__global__ __launch_bounds__(256) void attn_logits_kernel(
    const float* __restrict__ q, const float* __restrict__ k,
    const float* __restrict__ adj, const float* __restrict__ R,
    float* __restrict__ M_out, float* __restrict__ rmax_out)
{
    AttnSmem* S = (AttnSmem*)attn_smem_raw;
    int tid = threadIdx.x, w = tid >> 5, lane = tid & 31;
    int b = blockIdx.y, l0 = blockIdx.x * 8;
    int z = blockIdx.z;

    for (int i = tid; i < 2048; i += 256) {
        int h = i >> 8, li = (i >> 5) & 7, d = i & 31;
        S->Qs[h][li][d] = q[((size_t)((b * 8 + h) * LL + l0 + li)) * 32 + d];
    }
    if (tid < 64) S->Rs[tid] = R[tid];

    float rmax[8];
    #pragma unroll
    for (int i = 0; i < 8; i++) rmax[i] = -INFINITY;
    __syncthreads();

    const int l = l0 + w;
    const float* kbase = k + (size_t)(b * 8 + w) * (LL * DD);  // head w

    for (int cch = z * 16; cch < z * 16 + 16; cch++) {
        int t0 = cch * 32;
        int buf = cch & 1;

        // stage K chunk (Ks[w] warp-private -> __syncwarp)
        #pragma unroll
        for (int j = 0; j < 8; j++) {
            int fi = j * 32 + lane;
            int t = fi >> 3, d4 = (fi & 7) * 4;
            *(float4*)&S->Ks[w][t][d4] =
                *(const float4*)(kbase + (size_t)(t0 + t) * DD + d4);
        }
        __syncwarp();

        // phase A: packed-f32x2 logits
        {
            unsigned long long acc2[8];
            #pragma unroll
            for (int li = 0; li < 8; li++) acc2[li] = 0ULL;
            #pragma unroll
            for (int d8 = 0; d8 < 32; d8 += 8) {
                const ulonglong2* kp = (const ulonglong2*)&S->Ks[w][lane][d8];
                ulonglong2 k0 = kp[0], k1 = kp[1];
                #pragma unroll
                for (int li = 0; li < 8; li++) {
                    const ulonglong2* qp = (const ulonglong2*)&S->Qs[w][li][d8];
                    ulonglong2 q0 = qp[0], q1 = qp[1];
                    FMA2(acc2[li], q0.x, k0.x); FMA2(acc2[li], q0.y, k0.y);
                    FMA2(acc2[li], q1.x, k1.x); FMA2(acc2[li], q1.y, k1.y);
                }
            }
            #pragma unroll
            for (int li = 0; li < 8; li++) {
                float lo, hi;
                UNPACK2(lo, hi, acc2[li]);
                float s = (lo + hi) * ATT_SCALE;
                S->Ss[buf][w][li][lane] = (s > 0.f) ? s : 0.01f * s;  // leaky
            }
        }
        __syncthreads();

        // phase B: mixing + mask + running max for row li = w
        {
            float sv[8];
            #pragma unroll
            for (int h = 0; h < 8; h++) sv[h] = S->Ss[buf][h][w][lane];
            int t = t0 + lane;
            #pragma unroll
            for (int i = 0; i < 8; i++) {
                float m = 0.f;
                #pragma unroll
                for (int h = 0; h < 8; h++) m += S->Rs[i * 8 + h] * sv[h];
                size_t idx = ((size_t)((b * 8 + i) * LL + l)) * LL + t;
                float a = adj[idx];
                float o = (a > 0.f) ? m : -INFINITY;
                M_out[idx] = o;
                rmax[i] = fmaxf(rmax[i], o);
            }
        }
    }

    #pragma unroll
    for (int i = 0; i < 8; i++) {
        float mx = rmax[i];
        #pragma unroll
        for (int off = 16; off; off >>= 1)
            mx = fmaxf(mx, __shfl_down_sync(0xffffffffu, mx, off));
        if (lane == 0) rmax_out[z * 32768 + (b * 8 + i) * LL + l] = mx;
    }
}

// ---------------------------------------------------------------------------
// K4 (FUSED): one row-wise pass over raw logits doing:
//   rinv = 1/sum_t exp(m - rmax)           (old rowsum_kernel)
//   A[l,t] = exp(m - rmax)*rinv, in place  (old norm_colsum write)
//   colacc[t] += exp(A[l,t]) partials      (old norm_colsum partial sums)
//   VM[l,:] = sum_{t: A>0} A[l,t]*xv[t,:]  (old spmm_weighted, same order)
// Block = (seg of 128 rows, bi). Warp handles 16 rows, full row in registers.
// ---------------------------------------------------------------------------
__global__ __launch_bounds__(256) void stats_fuse_kernel(
    float* __restrict__ A, const float* __restrict__ rmaxp,
    const float* __restrict__ XV, float* __restrict__ pcol,
    float* __restrict__ VM)
{
    __shared__ float colsmem[8][1024];
    int tid = threadIdx.x;
    int w = tid >> 5, lane = tid & 31;
    int seg = blockIdx.x, bi = blockIdx.y;
    int b = bi >> 3, hh = bi & 7;
    float* base = A + (size_t)bi * (LL * LL);
    const float* Xb = XV + (size_t)bi * (LL * DD);

    float colacc[32];
    #pragma unroll
    for (int i = 0; i < 32; i++) colacc[i] = 0.f;

    for (int j = 0; j < 16; j++) {
        int row = seg * 128 + j * 8 + w;
        float mx = fmaxf(rmaxp[bi * LL + row], rmaxp[32768 + bi * LL + row]);
        float* rp = base + (size_t)row * LL;

        float4 v[8];
        #pragma unroll
        for (int q = 0; q < 8; q++)
            v[q] = *(const float4*)&rp[q * 128 + lane * 4];

        // exp(m - mx) in place (masked -inf -> exact 0)
        #pragma unroll
        for (int q = 0; q < 8; q++) {
            v[q].x = __expf(v[q].x - mx); v[q].y = __expf(v[q].y - mx);
            v[q].z = __expf(v[q].z - mx); v[q].w = __expf(v[q].w - mx);
        }

        // row sum (same order as old rowsum_kernel)
        float sum = 0.f;
        #pragma unroll
        for (int q = 0; q < 8; q++)
            sum += v[q].x + v[q].y + v[q].z + v[q].w;
        #pragma unroll
        for (int off = 16; off; off >>= 1)
            sum += __shfl_down_sync(0xffffffffu, sum, off);
        float rinv = 1.f / __shfl_sync(0xffffffffu, sum, 0);

        // normalize + write + column partials + sparse gather (A @ xv)
        float acc0 = 0.f, acc1 = 0.f;
        #pragma unroll
        for (int q = 0; q < 8; q++) {
            float4 a;
            a.x = v[q].x * rinv; a.y = v[q].y * rinv;
            a.z = v[q].z * rinv; a.w = v[q].w * rinv;
            *(float4*)&rp[q * 128 + lane * 4] = a;
            colacc[q * 4 + 0] += __expf(a.x);
            colacc[q * 4 + 1] += __expf(a.y);
            colacc[q * 4 + 2] += __expf(a.z);
            colacc[q * 4 + 3] += __expf(a.w);
            #pragma unroll
            for (int c = 0; c < 4; c++) {
                float gv = (c == 0) ? a.x : (c == 1) ? a.y : (c == 2) ? a.z : a.w;
                unsigned m = __ballot_sync(0xffffffffu, gv > 0.f);
                while (m) {
                    int j2 = __ffs(m) - 1; m &= m - 1;
                    float av = __shfl_sync(0xffffffffu, gv, j2);
                    acc0 += av * Xb[(q * 128 + j2 * 4 + c) * DD + lane];
                    if (m) {
                        j2 = __ffs(m) - 1; m &= m - 1;
                        float av2 = __shfl_sync(0xffffffffu, gv, j2);
                        acc1 += av2 * Xb[(q * 128 + j2 * 4 + c) * DD + lane];
                    }
                }
            }
        }
        VM[(size_t)b * (LL * DIMM) + (size_t)row * DIMM + hh * 32 + lane]
            = acc0 + acc1;
    }

    // stash per-warp column partials, reduce across warps (fixed order)
    #pragma unroll
    for (int q = 0; q < 8; q++)
        *(float4*)&colsmem[w][q * 128 + lane * 4] =
            make_float4(colacc[q*4], colacc[q*4+1], colacc[q*4+2], colacc[q*4+3]);
    __syncthreads();
    for (int t = tid; t < 1024; t += 256) {
        float s = 0.f;
        #pragma unroll
        for (int ww = 0; ww < 8; ww++) s += colsmem[ww][t];
        pcol[((size_t)seg * 32 + bi) * LL + t] = s;
    }
}

// ---------------------------------------------------------------------------
// K5: Ar[b,i,t,l] = exp(A[b,i,l,t]) / colsum(t)  (tiled transpose; 8 partials)
// ---------------------------------------------------------------------------
__global__ __launch_bounds__(256) void transpose_exp_kernel(
    const float* __restrict__ A, const float* __restrict__ pcol,
    float* __restrict__ Ar)
{
    __shared__ float Ts[32][33];
    int bi = blockIdx.z;
    int l0 = blockIdx.x * 32, t0 = blockIdx.y * 32;
    int lane = threadIdx.x & 31, wr = threadIdx.x >> 5;
    const float* base = A + (size_t)bi * (LL * LL);
    float* obase = Ar + (size_t)bi * (LL * LL);
    #pragma unroll
    for (int j = 0; j < 4; j++) {
        int lr = wr + j * 8;
        Ts[lr][lane] = base[(size_t)(l0 + lr) * LL + t0 + lane];
    }
    __syncthreads();
    #pragma unroll
    for (int j = 0; j < 4; j++) {
        int tr = wr + j * 8;
        int tt = t0 + tr;
        float cs = 0.f;
        #pragma unroll
        for (int seg = 0; seg < 8; seg++)
            cs += pcol[((size_t)seg * 32 + bi) * LL + tt];
        obase[(size_t)tt * LL + l0 + lane] = __expf(Ts[lane][tr]) * (1.f / cs);
    }
}

// ---------------------------------------------------------------------------
// K6: Out[r,n] = sum_m gelu(Vm[r,m]) * Wp[m,n], packed f32x2 inner loop.
// ---------------------------------------------------------------------------
__device__ __forceinline__ float gelu_exact(float v)
{
    return 0.5f * v * (1.f + erff(v * 0.70710678118654752f));
}

__global__ __launch_bounds__(256) void out_gemm(
    const float* __restrict__ V0, const float* __restrict__ V1,
    const float* __restrict__ Wp,
    float* __restrict__ O0, float* __restrict__ O1)
{
    __shared__ float Gs[32][68];
    __shared__ float Ws[1024];
    const float* Vm = blockIdx.z ? V1 : V0;
    float* Out = blockIdx.z ? O1 : O0;
    int tid = threadIdx.x;
    int r0 = blockIdx.x * 64, n0 = blockIdx.y * 32;
    int d = tid & 31, rg = tid >> 5;
    int rrow = tid >> 2, cseg = (tid & 3) * 8;

    unsigned long long acc2[4];
    #pragma unroll
    for (int j = 0; j < 4; j++) acc2[j] = 0ULL;

    for (int k0 = 0; k0 < DIMM; k0 += 32) {
        const float* vrow = Vm + (size_t)(r0 + rrow) * DIMM + k0 + cseg;
        float4 a0 = *(const float4*)(vrow);
        float4 a1 = *(const float4*)(vrow + 4);
        Gs[cseg+0][rrow] = gelu_exact(a0.x); Gs[cseg+1][rrow] = gelu_exact(a0.y);
        Gs[cseg+2][rrow] = gelu_exact(a0.z); Gs[cseg+3][rrow] = gelu_exact(a0.w);
        Gs[cseg+4][rrow] = gelu_exact(a1.x); Gs[cseg+5][rrow] = gelu_exact(a1.y);
        Gs[cseg+6][rrow] = gelu_exact(a1.z); Gs[cseg+7][rrow] = gelu_exact(a1.w);
        *(float4*)&Ws[(tid >> 3) * 32 + (tid & 7) * 4] =
            *(const float4*)(Wp + (size_t)(k0 + (tid >> 3)) * DIMM + n0 + (tid & 7) * 4);
        __syncthreads();

        #pragma unroll
        for (int kk = 0; kk < 32; kk++) {
            float bv = Ws[kk * 32 + d];
            unsigned long long bvv;
            DUP2(bvv, bv);
            const ulonglong2* gp = (const ulonglong2*)&Gs[kk][rg * 8];
            ulonglong2 g0 = gp[0];
            ulonglong2 g1 = gp[1];
            FMA2(acc2[0], g0.x, bvv); FMA2(acc2[1], g0.y, bvv);
            FMA2(acc2[2], g1.x, bvv); FMA2(acc2[3], g1.y, bvv);
        }
        __syncthreads();
    }
    #pragma unroll
    for (int j = 0; j < 4; j++) {
        float lo, hi;
        UNPACK2(lo, hi, acc2[j]);
        Out[(size_t)(r0 + rg * 8 + 2*j    ) * DIMM + n0 + d] = lo;
        Out[(size_t)(r0 + rg * 8 + 2*j + 1) * DIMM + n0 + d] = hi;
    }
}

// ---------------------------------------------------------------------------
// Launch. Output layout (float32, reference return order):
//   out [4,1024,256] | out_resize [4,1024,256] | A [4,8,1024,1024] | Ar [...]
// ---------------------------------------------------------------------------
extern "C" void kernel_launch(void* const* d_in, const int* in_sizes, int n_in,
                              void* d_out, int out_size)
{
    const float* x    = (const float*)d_in[0];
    const float* rx   = (const float*)d_in[1];
    const float* adj  = (const float*)d_in[2];
    const float* adjr = (const float*)d_in[3];
    const float* Wq   = (const float*)d_in[4];
    const float* Wk   = (const float*)d_in[5];
    const float* Wv   = (const float*)d_in[6];
    const float* R    = (const float*)d_in[7];
    const float* Wp   = (const float*)d_in[8];

    float* out  = (float*)d_out;
    float* outr = out + (size_t)BB * LL * DIMM;
    float* A    = out + (size_t)2 * BB * LL * DIMM;
    float* Ar   = A + (size_t)BB * HH * LL * LL;

    float* s = nullptr;
    cudaGetSymbolAddress((void**)&s, g_scratch);

    cudaFuncSetAttribute(attn_logits_kernel,
                         cudaFuncAttributeMaxDynamicSharedMemorySize,
                         (int)sizeof(AttnSmem));

    // K1: projections (xq, xk, xv, rv)
    proj_kernel<<<dim3(4096, 4), 256>>>(x, rx, Wq, Wk, Wv, s);

    // K2: q = adj @ xq ; k = adjr @ xk  -- sparse binary gather (exact)
    spmm_binary<<<dim3(128, 32, 2), 256>>>(adj,  s + OFF_XQ, s + OFF_Q,
                                           adjr, s + OFF_XK, s + OFF_K);

    // K3: logits + mask -> raw m in A buffer; per-half row max to scratch
    attn_logits_kernel<<<dim3(128, 4, 2), 256, sizeof(AttnSmem)>>>(
        s + OFF_Q, s + OFF_K, adj, R, A, s + OFF_RMAX);

    // K4: fused rowsum + normalize + column partials + v = A @ xv
    stats_fuse_kernel<<<dim3(8, 32), 256>>>(A, s + OFF_RMAX, s + OFF_XV,
                                            s + OFF_PCOL, s + OFF_VM);

    // K5: dual softmax on transpose -> Ar (combines 8 partials)
    transpose_exp_kernel<<<dim3(32, 32, 32), 256>>>(A, s + OFF_PCOL, Ar);

    // vr = Ar @ rv -- dense
    gemm_dense<<<dim3(8, 32), 256>>>(Ar, s + OFF_RV, s + OFF_VRM,
                                     (size_t)LL * DIMM, (size_t)DD, DIMM);

    // K6: out = gelu(v) @ Wp ; out_resize = gelu(vr) @ Wp
    out_gemm<<<dim3(64, 8, 2), 256>>>(s + OFF_VM, s + OFF_VRM, Wp, out, outr);
}

// round 8
// speedup vs baseline: 1.1123x; 1.1123x over previous
#include <cuda_runtime.h>
#include <math.h>

#define BB 4
#define HH 8
#define LL 1024
#define DD 32
#define DIMM 256
#define ATT_SCALE 0.0625f   // DIM^-0.5 = 1/16

#define M1 1048576
// scratch layout (floats)
#define OFF_XQ  (0*M1)
#define OFF_XK  (1*M1)
#define OFF_XV  (2*M1)
#define OFF_RV  (3*M1)
#define OFF_Q   (4*M1)
#define OFF_K   (5*M1)
#define OFF_VM  (6*M1)
#define OFF_VRM (7*M1)
#define OFF_PCOL  (8*M1)                    // 4 segs x 32 bi x 1024 t = 131072
#define OFF_RMAX  (8*M1 + 131072)           // 2 t-halves x 32768 rows = 65536
#define OFF_RMAXC (8*M1 + 196608)           // combined max, 32768
#define OFF_RINV  (8*M1 + 229376)           // 32768

__device__ float g_scratch[8*M1 + 262144];

// packed fp32x2 helpers (sm_100+)
#define FMA2(acc, a, b) \
    asm("fma.rn.f32x2 %0, %1, %2, %0;" : "+l"(acc) : "l"(a), "l"(b))
#define DUP2(dst, v) \
    asm("mov.b64 %0, {%1, %1};" : "=l"(dst) : "f"(v))
#define UNPACK2(lo, hi, v) \
    asm("mov.b64 {%0, %1}, %2;" : "=f"(lo), "=f"(hi) : "l"(v))

// ---------------------------------------------------------------------------
// K1: per-head projections  dst[b,h,t,d] = sum_dp src[b,t,h*32+dp] * W[dp,d]
// ---------------------------------------------------------------------------
__global__ __launch_bounds__(256) void proj_kernel(
    const float* __restrict__ x, const float* __restrict__ rx,
    const float* __restrict__ Wq, const float* __restrict__ Wk,
    const float* __restrict__ Wv, float* __restrict__ scratch)
{
    int tid = threadIdx.x;
    int which = blockIdx.y;
    const float* src = (which == 0 || which == 2) ? x : rx;
    const float* W = (which == 0) ? Wq : ((which == 1) ? Wk : Wv);
    float* dst = scratch + (size_t)which * M1;

    __shared__ float Ws[1024];
    __shared__ float Xs[8][32];
    for (int i = tid; i < 1024; i += 256) Ws[i] = W[i];

    int r = blockIdx.x * 8 + (tid >> 5);   // r = (b*8+h)*1024 + t
    int d = tid & 31;
    int b = r >> 13;
    int h = (r >> 10) & 7;
    int t = r & 1023;
    Xs[tid >> 5][d] = src[((size_t)(b * LL + t)) * DIMM + h * 32 + d];
    __syncthreads();

    float acc = 0.f;
    #pragma unroll
    for (int dp = 0; dp < 32; dp++) acc += Xs[tid >> 5][dp] * Ws[dp * 32 + d];
    dst[(size_t)r * 32 + d] = acc;
}

// ---------------------------------------------------------------------------
// K2: SPARSE binary gather-sum:  O[bh][l][d] = sum_{t: G[bh][l][t] > 0} X[bh][t][d]
// G values exactly 0.0/1.0 -> zero-skip is bit-exact.
// ---------------------------------------------------------------------------
__global__ __launch_bounds__(256) void spmm_binary(
    const float* __restrict__ G0, const float* __restrict__ X0, float* __restrict__ O0,
    const float* __restrict__ G1, const float* __restrict__ X1, float* __restrict__ O1)
{
    int lane = threadIdx.x & 31, w = threadIdx.x >> 5;
    int l = blockIdx.x * 8 + w;
    int bh = blockIdx.y;
    const float* G = (blockIdx.z ? G1 : G0) + (size_t)bh * (LL * LL) + (size_t)l * LL;
    const float* X = (blockIdx.z ? X1 : X0) + (size_t)bh * (LL * DD);
    float* O = (blockIdx.z ? O1 : O0) + (size_t)bh * (LL * DD);

    float acc0 = 0.f, acc1 = 0.f;
    for (int t0 = 0; t0 < LL; t0 += 128) {
        float4 g = *(const float4*)&G[t0 + lane * 4];
        #pragma unroll
        for (int c = 0; c < 4; c++) {
            float gv = (c == 0) ? g.x : (c == 1) ? g.y : (c == 2) ? g.z : g.w;
            unsigned m = __ballot_sync(0xffffffffu, gv > 0.f);
            while (m) {
                int j = __ffs(m) - 1; m &= m - 1;
                acc0 += X[(t0 + j * 4 + c) * DD + lane];
                if (m) {
                    j = __ffs(m) - 1; m &= m - 1;
                    acc1 += X[(t0 + j * 4 + c) * DD + lane];
                }
            }
        }
    }
    O[(size_t)l * DD + lane] = acc0 + acc1;
}

// ---------------------------------------------------------------------------
// K2b: SPARSE weighted gather:  VM[b,l,h*32+d] = sum_{t: A[bh][l][t] > 0} A*X
// ---------------------------------------------------------------------------
__global__ __launch_bounds__(256) void spmm_weighted(
    const float* __restrict__ A, const float* __restrict__ X, float* __restrict__ O)
{
    int lane = threadIdx.x & 31, w = threadIdx.x >> 5;
    int l = blockIdx.x * 8 + w;
    int bh = blockIdx.y;
    int b = bh >> 3, h = bh & 7;
    const float* G = A + (size_t)bh * (LL * LL) + (size_t)l * LL;
    const float* Xb = X + (size_t)bh * (LL * DD);

    float acc0 = 0.f, acc1 = 0.f;
    for (int t0 = 0; t0 < LL; t0 += 128) {
        float4 g = *(const float4*)&G[t0 + lane * 4];
        #pragma unroll
        for (int c = 0; c < 4; c++) {
            float gv = (c == 0) ? g.x : (c == 1) ? g.y : (c == 2) ? g.z : g.w;
            unsigned m = __ballot_sync(0xffffffffu, gv > 0.f);
            while (m) {
                int j = __ffs(m) - 1; m &= m - 1;
                float av = __shfl_sync(0xffffffffu, gv, j);
                acc0 += av * Xb[(t0 + j * 4 + c) * DD + lane];
                if (m) {
                    j = __ffs(m) - 1; m &= m - 1;
                    float av2 = __shfl_sync(0xffffffffu, gv, j);
                    acc1 += av2 * Xb[(t0 + j * 4 + c) * DD + lane];
                }
            }
        }
    }
    O[(size_t)b * (LL * DIMM) + (size_t)l * DIMM + h * 32 + lane] = acc0 + acc1;
}

// ---------------------------------------------------------------------------
// K2c: DENSE per-(b,h) SGEMM (vr = Ar @ rv; Ar is dense).
// 64x32 tile (512 blocks, 3.5/SM), packed f32x2 FMA, register prefetch.
// ---------------------------------------------------------------------------
__global__ __launch_bounds__(256) void gemm_dense(
    const float* __restrict__ Amat, const float* __restrict__ Bm,
    float* __restrict__ C, size_t c_b_stride, size_t c_h_stride, int c_row_stride)
{
    __shared__ float Ast[32][68];   // transposed A tile [k][row]
    __shared__ float Bs[1024];      // [k][d]

    int tid = threadIdx.x;
    int bh = blockIdx.y;
    const float* A  = Amat + (size_t)bh * (LL * LL);
    const float* Bb = Bm + (size_t)bh * (LL * DD);
    float* Cb = C + (size_t)(bh >> 3) * c_b_stride + (size_t)(bh & 7) * c_h_stride;
    int l0 = blockIdx.x * 64;

    int d = tid & 31, rg = tid >> 5;            // 8 rows rg*8..rg*8+7, col d
    int lrow = tid >> 2, cseg = (tid & 3) * 8;  // staging: quarter-row/thread

    unsigned long long acc2[4];
    #pragma unroll
    for (int j = 0; j < 4; j++) acc2[j] = 0ULL;

    float4 pa0, pa1, pb;
    {
        const float* p = A + (size_t)(l0 + lrow) * LL + cseg;
        pa0 = *(const float4*)(p);
        pa1 = *(const float4*)(p + 4);
        pb  = *(const float4*)(Bb + tid * 4);
    }

    for (int c = 0; c < 32; c++) {
        Ast[cseg+0][lrow]=pa0.x; Ast[cseg+1][lrow]=pa0.y;
        Ast[cseg+2][lrow]=pa0.z; Ast[cseg+3][lrow]=pa0.w;
        Ast[cseg+4][lrow]=pa1.x; Ast[cseg+5][lrow]=pa1.y;
        Ast[cseg+6][lrow]=pa1.z; Ast[cseg+7][lrow]=pa1.w;
        *(float4*)&Bs[tid * 4] = pb;
        __syncthreads();

        if (c < 31) {
            int k0 = (c + 1) * 32;
            const float* p = A + (size_t)(l0 + lrow) * LL + k0 + cseg;
            pa0 = *(const float4*)(p);
            pa1 = *(const float4*)(p + 4);
            pb  = *(const float4*)(Bb + (size_t)k0 * DD + tid * 4);
        }

        #pragma unroll
        for (int kk = 0; kk < 32; kk++) {
            float bv = Bs[kk * 32 + d];
            unsigned long long bvv;
            DUP2(bvv, bv);
            const ulonglong2* ap = (const ulonglong2*)&Ast[kk][rg * 8];
            ulonglong2 q0 = ap[0];
            ulonglong2 q1 = ap[1];
            FMA2(acc2[0], q0.x, bvv); FMA2(acc2[1], q0.y, bvv);
            FMA2(acc2[2], q1.x, bvv); FMA2(acc2[3], q1.y, bvv);
        }
        __syncthreads();
    }

    #pragma unroll
    for (int j = 0; j < 4; j++) {
        float lo, hi;
        UNPACK2(lo, hi, acc2[j]);
        Cb[(size_t)(l0 + rg * 8 + 2*j    ) * c_row_stride + d] = lo;
        Cb[(size_t)(l0 + rg * 8 + 2*j + 1) * c_row_stride + d] = hi;
    }
}

// ---------------------------------------------------------------------------
// K3: logits + leaky + R-mix + mask -> raw logits (or -inf) in M_out; partial
// row max per t-half to rmax_out. grid.z = t-half (512 t's each).
// ---------------------------------------------------------------------------
struct AttnSmem {
    float Qs[8][8][32];
    float Ss[2][8][8][32];
    float Ks[8][32][36];
    float Rs[64];
};

extern __shared__ unsigned char attn_smem_raw[];

__global__ __launch_bounds__(256) void attn_logits_kernel(
    const float* __restrict__ q, const float* __restrict__ k,
    const float* __restrict__ adj, const float* __restrict__ R,
    float* __restrict__ M_out, float* __restrict__ rmax_out)
{
    AttnSmem* S = (AttnSmem*)attn_smem_raw;
    int tid = threadIdx.x, w = tid >> 5, lane = tid & 31;
    int b = blockIdx.y, l0 = blockIdx.x * 8;
    int z = blockIdx.z;

    for (int i = tid; i < 2048; i += 256) {
        int h = i >> 8, li = (i >> 5) & 7, d = i & 31;
        S->Qs[h][li][d] = q[((size_t)((b * 8 + h) * LL + l0 + li)) * 32 + d];
    }
    if (tid < 64) S->Rs[tid] = R[tid];

    float rmax[8];
    #pragma unroll
    for (int i = 0; i < 8; i++) rmax[i] = -INFINITY;
    __syncthreads();

    const int l = l0 + w;
    const float* kbase = k + (size_t)(b * 8 + w) * (LL * DD);  // head w

    for (int cch = z * 16; cch < z * 16 + 16; cch++) {
        int t0 = cch * 32;
        int buf = cch & 1;

        // stage K chunk (Ks[w] warp-private -> __syncwarp)
        #pragma unroll
        for (int j = 0; j < 8; j++) {
            int fi = j * 32 + lane;
            int t = fi >> 3, d4 = (fi & 7) * 4;
            *(float4*)&S->Ks[w][t][d4] =
                *(const float4*)(kbase + (size_t)(t0 + t) * DD + d4);
        }
        __syncwarp();

        // phase A: packed-f32x2 logits
        {
            unsigned long long acc2[8];
            #pragma unroll
            for (int li = 0; li < 8; li++) acc2[li] = 0ULL;
            #pragma unroll
            for (int d8 = 0; d8 < 32; d8 += 8) {
                const ulonglong2* kp = (const ulonglong2*)&S->Ks[w][lane][d8];
                ulonglong2 k0 = kp[0], k1 = kp[1];
                #pragma unroll
                for (int li = 0; li < 8; li++) {
                    const ulonglong2* qp = (const ulonglong2*)&S->Qs[w][li][d8];
                    ulonglong2 q0 = qp[0], q1 = qp[1];
                    FMA2(acc2[li], q0.x, k0.x); FMA2(acc2[li], q0.y, k0.y);
                    FMA2(acc2[li], q1.x, k1.x); FMA2(acc2[li], q1.y, k1.y);
                }
            }
            #pragma unroll
            for (int li = 0; li < 8; li++) {
                float lo, hi;
                UNPACK2(lo, hi, acc2[li]);
                float s = (lo + hi) * ATT_SCALE;
                S->Ss[buf][w][li][lane] = (s > 0.f) ? s : 0.01f * s;  // leaky
            }
        }
        __syncthreads();

        // phase B: mixing + mask + running max for row li = w
        {
            float sv[8];
            #pragma unroll
            for (int h = 0; h < 8; h++) sv[h] = S->Ss[buf][h][w][lane];
            int t = t0 + lane;
            #pragma unroll
            for (int i = 0; i < 8; i++) {
                float m = 0.f;
                #pragma unroll
                for (int h = 0; h < 8; h++) m += S->Rs[i * 8 + h] * sv[h];
                size_t idx = ((size_t)((b * 8 + i) * LL + l)) * LL + t;
                float a = adj[idx];
                float o = (a > 0.f) ? m : -INFINITY;
                M_out[idx] = o;
                rmax[i] = fmaxf(rmax[i], o);
            }
        }
    }

    #pragma unroll
    for (int i = 0; i < 8; i++) {
        float mx = rmax[i];
        #pragma unroll
        for (int off = 16; off; off >>= 1)
            mx = fmaxf(mx, __shfl_down_sync(0xffffffffu, mx, off));
        if (lane == 0) rmax_out[z * 32768 + (b * 8 + i) * LL + l] = mx;
    }
}

// ---------------------------------------------------------------------------
// K3b: combine per-half maxes; rinv[row] = 1 / sum_t exp(M[row,t] - mx)
// ---------------------------------------------------------------------------
__global__ __launch_bounds__(256) void rowsum_kernel(
    const float* __restrict__ M, const float* __restrict__ rmaxp,
    float* __restrict__ rmaxc, float* __restrict__ rinv)
{
    int row = blockIdx.x * 8 + (threadIdx.x >> 5);
    int lane = threadIdx.x & 31;
    const float* r = M + (size_t)row * LL;
    float mx = fmaxf(rmaxp[row], rmaxp[32768 + row]);
    float sum = 0.f;
    #pragma unroll
    for (int j = 0; j < 8; j++) {
        float4 v = *(const float4*)(r + (j * 32 + lane) * 4);
        sum += __expf(v.x - mx) + __expf(v.y - mx)
             + __expf(v.z - mx) + __expf(v.w - mx);
    }
    #pragma unroll
    for (int off = 16; off; off >>= 1)
        sum += __shfl_down_sync(0xffffffffu, sum, off);
    if (lane == 0) { rmaxc[row] = mx; rinv[row] = 1.f / sum; }
}

// ---------------------------------------------------------------------------
// K4: normalize A in place + partial transposed-softmax column sums.
// grid.z = row segment (256 rows each); partials to pcol[seg][bi][t].
// ---------------------------------------------------------------------------
__global__ __launch_bounds__(256) void norm_colsum_kernel(
    float* __restrict__ A, const float* __restrict__ rmax,
    const float* __restrict__ rinv, float* __restrict__ pcol)
{
    int bi = blockIdx.y;
    int seg = blockIdx.z;
    int t = blockIdx.x * 256 + threadIdx.x;
    float* base = A + (size_t)bi * (LL * LL);
    const float* mx = rmax + bi * LL;
    const float* iv = rinv + bi * LL;

    int lr0 = seg * 256;
    float s0 = 0.f, s1 = 0.f, s2 = 0.f, s3 = 0.f;
    for (int lr = lr0; lr < lr0 + 256; lr += 4) {
        float m0 = base[(size_t)(lr + 0) * LL + t];
        float m1 = base[(size_t)(lr + 1) * LL + t];
        float m2 = base[(size_t)(lr + 2) * LL + t];
        float m3 = base[(size_t)(lr + 3) * LL + t];
        float a0 = __expf(m0 - mx[lr + 0]) * iv[lr + 0];
        float a1 = __expf(m1 - mx[lr + 1]) * iv[lr + 1];
        float a2 = __expf(m2 - mx[lr + 2]) * iv[lr + 2];
        float a3 = __expf(m3 - mx[lr + 3]) * iv[lr + 3];
        base[(size_t)(lr + 0) * LL + t] = a0;
        base[(size_t)(lr + 1) * LL + t] = a1;
        base[(size_t)(lr + 2) * LL + t] = a2;
        base[(size_t)(lr + 3) * LL + t] = a3;
        s0 += __expf(a0); s1 += __expf(a1);
        s2 += __expf(a2); s3 += __expf(a3);
    }
    pcol[(size_t)(seg * 32 + bi) * LL + t] = (s0 + s1) + (s2 + s3);
}

// ---------------------------------------------------------------------------
// K5: Ar[b,i,t,l] = exp(A[b,i,l,t]) / colsum(t)  (tiled transpose; 4 partials)
// ---------------------------------------------------------------------------
__global__ __launch_bounds__(256) void transpose_exp_kernel(
    const float* __restrict__ A, const float* __restrict__ pcol,
    float* __restrict__ Ar)
{
    __shared__ float Ts[32][33];
    int bi = blockIdx.z;
    int l0 = blockIdx.x * 32, t0 = blockIdx.y * 32;
    int lane = threadIdx.x & 31, wr = threadIdx.x >> 5;
    const float* base = A + (size_t)bi * (LL * LL);
    float* obase = Ar + (size_t)bi * (LL * LL);
    #pragma unroll
    for (int j = 0; j < 4; j++) {
        int lr = wr + j * 8;
        Ts[lr][lane] = base[(size_t)(l0 + lr) * LL + t0 + lane];
    }
    __syncthreads();
    #pragma unroll
    for (int j = 0; j < 4; j++) {
        int tr = wr + j * 8;
        int tt = t0 + tr;
        float rc = 1.f / (pcol[(size_t)(0 * 32 + bi) * LL + tt]
                        + pcol[(size_t)(1 * 32 + bi) * LL + tt]
                        + pcol[(size_t)(2 * 32 + bi) * LL + tt]
                        + pcol[(size_t)(3 * 32 + bi) * LL + tt]);
        obase[(size_t)tt * LL + l0 + lane] = __expf(Ts[lane][tr]) * rc;
    }
}

// ---------------------------------------------------------------------------
// K6: Out[r,n] = sum_m gelu(Vm[r,m]) * Wp[m,n], packed f32x2 inner loop.
// ---------------------------------------------------------------------------
__device__ __forceinline__ float gelu_exact(float v)
{
    return 0.5f * v * (1.f + erff(v * 0.70710678118654752f));
}

__global__ __launch_bounds__(256) void out_gemm(
    const float* __restrict__ V0, const float* __restrict__ V1,
    const float* __restrict__ Wp,
    float* __restrict__ O0, float* __restrict__ O1)
{
    __shared__ float Gs[32][68];
    __shared__ float Ws[1024];
    const float* Vm = blockIdx.z ? V1 : V0;
    float* Out = blockIdx.z ? O1 : O0;
    int tid = threadIdx.x;
    int r0 = blockIdx.x * 64, n0 = blockIdx.y * 32;
    int d = tid & 31, rg = tid >> 5;
    int rrow = tid >> 2, cseg = (tid & 3) * 8;

    unsigned long long acc2[4];
    #pragma unroll
    for (int j = 0; j < 4; j++) acc2[j] = 0ULL;

    for (int k0 = 0; k0 < DIMM; k0 += 32) {
        const float* vrow = Vm + (size_t)(r0 + rrow) * DIMM + k0 + cseg;
        float4 a0 = *(const float4*)(vrow);
        float4 a1 = *(const float4*)(vrow + 4);
        Gs[cseg+0][rrow] = gelu_exact(a0.x); Gs[cseg+1][rrow] = gelu_exact(a0.y);
        Gs[cseg+2][rrow] = gelu_exact(a0.z); Gs[cseg+3][rrow] = gelu_exact(a0.w);
        Gs[cseg+4][rrow] = gelu_exact(a1.x); Gs[cseg+5][rrow] = gelu_exact(a1.y);
        Gs[cseg+6][rrow] = gelu_exact(a1.z); Gs[cseg+7][rrow] = gelu_exact(a1.w);
        *(float4*)&Ws[(tid >> 3) * 32 + (tid & 7) * 4] =
            *(const float4*)(Wp + (size_t)(k0 + (tid >> 3)) * DIMM + n0 + (tid & 7) * 4);
        __syncthreads();

        #pragma unroll
        for (int kk = 0; kk < 32; kk++) {
            float bv = Ws[kk * 32 + d];
            unsigned long long bvv;
            DUP2(bvv, bv);
            const ulonglong2* gp = (const ulonglong2*)&Gs[kk][rg * 8];
            ulonglong2 g0 = gp[0];
            ulonglong2 g1 = gp[1];
            FMA2(acc2[0], g0.x, bvv); FMA2(acc2[1], g0.y, bvv);
            FMA2(acc2[2], g1.x, bvv); FMA2(acc2[3], g1.y, bvv);
        }
        __syncthreads();
    }
    #pragma unroll
    for (int j = 0; j < 4; j++) {
        float lo, hi;
        UNPACK2(lo, hi, acc2[j]);
        Out[(size_t)(r0 + rg * 8 + 2*j    ) * DIMM + n0 + d] = lo;
        Out[(size_t)(r0 + rg * 8 + 2*j + 1) * DIMM + n0 + d] = hi;
    }
}

// ---------------------------------------------------------------------------
// Launch. Output layout (float32, reference return order):
//   out [4,1024,256] | out_resize [4,1024,256] | A [4,8,1024,1024] | Ar [...]
// ---------------------------------------------------------------------------
extern "C" void kernel_launch(void* const* d_in, const int* in_sizes, int n_in,
                              void* d_out, int out_size)
{
    const float* x    = (const float*)d_in[0];
    const float* rx   = (const float*)d_in[1];
    const float* adj  = (const float*)d_in[2];
    const float* adjr = (const float*)d_in[3];
    const float* Wq   = (const float*)d_in[4];
    const float* Wk   = (const float*)d_in[5];
    const float* Wv   = (const float*)d_in[6];
    const float* R    = (const float*)d_in[7];
    const float* Wp   = (const float*)d_in[8];

    float* out  = (float*)d_out;
    float* outr = out + (size_t)BB * LL * DIMM;
    float* A    = out + (size_t)2 * BB * LL * DIMM;
    float* Ar   = A + (size_t)BB * HH * LL * LL;

    float* s = nullptr;
    cudaGetSymbolAddress((void**)&s, g_scratch);

    cudaFuncSetAttribute(attn_logits_kernel,
                         cudaFuncAttributeMaxDynamicSharedMemorySize,
                         (int)sizeof(AttnSmem));

    // K1: projections (xq, xk, xv, rv)
    proj_kernel<<<dim3(4096, 4), 256>>>(x, rx, Wq, Wk, Wv, s);

    // K2: q = adj @ xq ; k = adjr @ xk  -- sparse binary gather (exact)
    spmm_binary<<<dim3(128, 32, 2), 256>>>(adj,  s + OFF_XQ, s + OFF_Q,
                                           adjr, s + OFF_XK, s + OFF_K);

    // K3: logits + mask -> raw m in A buffer; per-half row max to scratch
    attn_logits_kernel<<<dim3(128, 4, 2), 256, sizeof(AttnSmem)>>>(
        s + OFF_Q, s + OFF_K, adj, R, A, s + OFF_RMAX);

    // K3b: combine maxes + row sums -> rmaxc, rinv
    rowsum_kernel<<<4096, 256>>>(A, s + OFF_RMAX, s + OFF_RMAXC, s + OFF_RINV);

    // K4: normalize A in place + partial column sums (4 segments)
    norm_colsum_kernel<<<dim3(4, 32, 4), 256>>>(A, s + OFF_RMAXC, s + OFF_RINV,
                                                s + OFF_PCOL);

    // K5: dual softmax on transpose -> Ar (combines partials)
    transpose_exp_kernel<<<dim3(32, 32, 32), 256>>>(A, s + OFF_PCOL, Ar);

    // v = A @ xv  -- sparse weighted gather (A zeros are exact)
    spmm_weighted<<<dim3(128, 32), 256>>>(A, s + OFF_XV, s + OFF_VM);

    // vr = Ar @ rv -- dense
    gemm_dense<<<dim3(16, 32), 256>>>(Ar, s + OFF_RV, s + OFF_VRM,
                                      (size_t)LL * DIMM, (size_t)DD, DIMM);

    // K6: out = gelu(v) @ Wp ; out_resize = gelu(vr) @ Wp
    out_gemm<<<dim3(64, 8, 2), 256>>>(s + OFF_VM, s + OFF_VRM, Wp, out, outr);
}

// round 9
// speedup vs baseline: 1.2264x; 1.1025x over previous
#include <cuda_runtime.h>
#include <math.h>

#define BB 4
#define HH 8
#define LL 1024
#define DD 32
#define DIMM 256
#define ATT_SCALE 0.0625f   // DIM^-0.5 = 1/16

#define M1 1048576
// scratch layout (floats)
#define OFF_XQ  (0*M1)
#define OFF_XK  (1*M1)
#define OFF_XV  (2*M1)
#define OFF_RV  (3*M1)
#define OFF_Q   (4*M1)
#define OFF_K   (5*M1)
#define OFF_VM  (6*M1)
#define OFF_VRM (7*M1)
#define OFF_PCOL  (8*M1)                    // 4 segs x 32 bi x 1024 t = 131072
#define OFF_RMAXC (8*M1 + 131072)           // full row max, 32768
#define OFF_RINV  (8*M1 + 163840)           // 32768

__device__ float g_scratch[8*M1 + 196608];

// packed fp32x2 helpers (sm_100+)
#define FMA2(acc, a, b) \
    asm("fma.rn.f32x2 %0, %1, %2, %0;" : "+l"(acc) : "l"(a), "l"(b))
#define DUP2(dst, v) \
    asm("mov.b64 %0, {%1, %1};" : "=l"(dst) : "f"(v))
#define UNPACK2(lo, hi, v) \
    asm("mov.b64 {%0, %1}, %2;" : "=f"(lo), "=f"(hi) : "l"(v))

// ---------------------------------------------------------------------------
// K1: per-head projections  dst[b,h,t,d] = sum_dp src[b,t,h*32+dp] * W[dp,d]
// ---------------------------------------------------------------------------
__global__ __launch_bounds__(256) void proj_kernel(
    const float* __restrict__ x, const float* __restrict__ rx,
    const float* __restrict__ Wq, const float* __restrict__ Wk,
    const float* __restrict__ Wv, float* __restrict__ scratch)
{
    int tid = threadIdx.x;
    int which = blockIdx.y;
    const float* src = (which == 0 || which == 2) ? x : rx;
    const float* W = (which == 0) ? Wq : ((which == 1) ? Wk : Wv);
    float* dst = scratch + (size_t)which * M1;

    __shared__ float Ws[1024];
    __shared__ float Xs[8][32];
    for (int i = tid; i < 1024; i += 256) Ws[i] = W[i];

    int r = blockIdx.x * 8 + (tid >> 5);   // r = (b*8+h)*1024 + t
    int d = tid & 31;
    int b = r >> 13;
    int h = (r >> 10) & 7;
    int t = r & 1023;
    Xs[tid >> 5][d] = src[((size_t)(b * LL + t)) * DIMM + h * 32 + d];
    __syncthreads();

    float acc = 0.f;
    #pragma unroll
    for (int dp = 0; dp < 32; dp++) acc += Xs[tid >> 5][dp] * Ws[dp * 32 + d];
    dst[(size_t)r * 32 + d] = acc;
}

// ---------------------------------------------------------------------------
// K2: SPARSE binary gather-sum:  O[bh][l][d] = sum_{t: G[bh][l][t] > 0} X[bh][t][d]
// ---------------------------------------------------------------------------
__global__ __launch_bounds__(256) void spmm_binary(
    const float* __restrict__ G0, const float* __restrict__ X0, float* __restrict__ O0,
    const float* __restrict__ G1, const float* __restrict__ X1, float* __restrict__ O1)
{
    int lane = threadIdx.x & 31, w = threadIdx.x >> 5;
    int l = blockIdx.x * 8 + w;
    int bh = blockIdx.y;
    const float* G = (blockIdx.z ? G1 : G0) + (size_t)bh * (LL * LL) + (size_t)l * LL;
    const float* X = (blockIdx.z ? X1 : X0) + (size_t)bh * (LL * DD);
    float* O = (blockIdx.z ? O1 : O0) + (size_t)bh * (LL * DD);

    float acc0 = 0.f, acc1 = 0.f;
    for (int t0 = 0; t0 < LL; t0 += 128) {
        float4 g = *(const float4*)&G[t0 + lane * 4];
        #pragma unroll
        for (int c = 0; c < 4; c++) {
            float gv = (c == 0) ? g.x : (c == 1) ? g.y : (c == 2) ? g.z : g.w;
            unsigned m = __ballot_sync(0xffffffffu, gv > 0.f);
            while (m) {
                int j = __ffs(m) - 1; m &= m - 1;
                acc0 += X[(t0 + j * 4 + c) * DD + lane];
                if (m) {
                    j = __ffs(m) - 1; m &= m - 1;
                    acc1 += X[(t0 + j * 4 + c) * DD + lane];
                }
            }
        }
    }
    O[(size_t)l * DD + lane] = acc0 + acc1;
}

// ---------------------------------------------------------------------------
// K2b: SPARSE weighted gather:  VM[b,l,h*32+d] = sum_{t: A[bh][l][t] > 0} A*X
// ---------------------------------------------------------------------------
__global__ __launch_bounds__(256) void spmm_weighted(
    const float* __restrict__ A, const float* __restrict__ X, float* __restrict__ O)
{
    int lane = threadIdx.x & 31, w = threadIdx.x >> 5;
    int l = blockIdx.x * 8 + w;
    int bh = blockIdx.y;
    int b = bh >> 3, h = bh & 7;
    const float* G = A + (size_t)bh * (LL * LL) + (size_t)l * LL;
    const float* Xb = X + (size_t)bh * (LL * DD);

    float acc0 = 0.f, acc1 = 0.f;
    for (int t0 = 0; t0 < LL; t0 += 128) {
        float4 g = *(const float4*)&G[t0 + lane * 4];
        #pragma unroll
        for (int c = 0; c < 4; c++) {
            float gv = (c == 0) ? g.x : (c == 1) ? g.y : (c == 2) ? g.z : g.w;
            unsigned m = __ballot_sync(0xffffffffu, gv > 0.f);
            while (m) {
                int j = __ffs(m) - 1; m &= m - 1;
                float av = __shfl_sync(0xffffffffu, gv, j);
                acc0 += av * Xb[(t0 + j * 4 + c) * DD + lane];
                if (m) {
                    j = __ffs(m) - 1; m &= m - 1;
                    float av2 = __shfl_sync(0xffffffffu, gv, j);
                    acc1 += av2 * Xb[(t0 + j * 4 + c) * DD + lane];
                }
            }
        }
    }
    O[(size_t)b * (LL * DIMM) + (size_t)l * DIMM + h * 32 + lane] = acc0 + acc1;
}

// ---------------------------------------------------------------------------
// K2c: DENSE per-(b,h) SGEMM (vr = Ar @ rv; Ar is dense). 64x32 tile.
// ---------------------------------------------------------------------------
__global__ __launch_bounds__(256) void gemm_dense(
    const float* __restrict__ Amat, const float* __restrict__ Bm,
    float* __restrict__ C, size_t c_b_stride, size_t c_h_stride, int c_row_stride)
{
    __shared__ float Ast[32][68];   // transposed A tile [k][row]
    __shared__ float Bs[1024];      // [k][d]

    int tid = threadIdx.x;
    int bh = blockIdx.y;
    const float* A  = Amat + (size_t)bh * (LL * LL);
    const float* Bb = Bm + (size_t)bh * (LL * DD);
    float* Cb = C + (size_t)(bh >> 3) * c_b_stride + (size_t)(bh & 7) * c_h_stride;
    int l0 = blockIdx.x * 64;

    int d = tid & 31, rg = tid >> 5;
    int lrow = tid >> 2, cseg = (tid & 3) * 8;

    unsigned long long acc2[4];
    #pragma unroll
    for (int j = 0; j < 4; j++) acc2[j] = 0ULL;

    float4 pa0, pa1, pb;
    {
        const float* p = A + (size_t)(l0 + lrow) * LL + cseg;
        pa0 = *(const float4*)(p);
        pa1 = *(const float4*)(p + 4);
        pb  = *(const float4*)(Bb + tid * 4);
    }

    for (int c = 0; c < 32; c++) {
        Ast[cseg+0][lrow]=pa0.x; Ast[cseg+1][lrow]=pa0.y;
        Ast[cseg+2][lrow]=pa0.z; Ast[cseg+3][lrow]=pa0.w;
        Ast[cseg+4][lrow]=pa1.x; Ast[cseg+5][lrow]=pa1.y;
        Ast[cseg+6][lrow]=pa1.z; Ast[cseg+7][lrow]=pa1.w;
        *(float4*)&Bs[tid * 4] = pb;
        __syncthreads();

        if (c < 31) {
            int k0 = (c + 1) * 32;
            const float* p = A + (size_t)(l0 + lrow) * LL + k0 + cseg;
            pa0 = *(const float4*)(p);
            pa1 = *(const float4*)(p + 4);
            pb  = *(const float4*)(Bb + (size_t)k0 * DD + tid * 4);
        }

        #pragma unroll
        for (int kk = 0; kk < 32; kk++) {
            float bv = Bs[kk * 32 + d];
            unsigned long long bvv;
            DUP2(bvv, bv);
            const ulonglong2* ap = (const ulonglong2*)&Ast[kk][rg * 8];
            ulonglong2 q0 = ap[0];
            ulonglong2 q1 = ap[1];
            FMA2(acc2[0], q0.x, bvv); FMA2(acc2[1], q0.y, bvv);
            FMA2(acc2[2], q1.x, bvv); FMA2(acc2[3], q1.y, bvv);
        }
        __syncthreads();
    }

    #pragma unroll
    for (int j = 0; j < 4; j++) {
        float lo, hi;
        UNPACK2(lo, hi, acc2[j]);
        Cb[(size_t)(l0 + rg * 8 + 2*j    ) * c_row_stride + d] = lo;
        Cb[(size_t)(l0 + rg * 8 + 2*j + 1) * c_row_stride + d] = hi;
    }
}

// ---------------------------------------------------------------------------
// K3a: S[bh][l][t] = leaky(ATT_SCALE * dot(q[bh][l], k[bh][t]))
// 64x64 tile, K=32 single pass, transposed smem (conflict-free), packed FMA.
// Thread: g = tid>>6 (l-group of 16), tl = tid&63 (one t). 16 outputs/thread.
// ---------------------------------------------------------------------------
__global__ __launch_bounds__(256) void qk_gemm(
    const float* __restrict__ q, const float* __restrict__ k,
    float* __restrict__ S)
{
    __shared__ float Qt[32][68];   // [d][l]
    __shared__ float Kt[32][68];   // [d][t]

    int tid = threadIdx.x;
    int bh = blockIdx.z;
    int t0 = blockIdx.x * 64, l0 = blockIdx.y * 64;
    const float* qb = q + (size_t)bh * (LL * DD);
    const float* kb = k + (size_t)bh * (LL * DD);

    // load + transpose: each thread 2 float4 from q, 2 from k
    {
        int r = tid >> 3, c = (tid & 7) * 4;
        float4 v;
        v = *(const float4*)(qb + (size_t)(l0 + r) * DD + c);
        Qt[c+0][r] = v.x; Qt[c+1][r] = v.y; Qt[c+2][r] = v.z; Qt[c+3][r] = v.w;
        v = *(const float4*)(qb + (size_t)(l0 + r + 32) * DD + c);
        Qt[c+0][r+32] = v.x; Qt[c+1][r+32] = v.y; Qt[c+2][r+32] = v.z; Qt[c+3][r+32] = v.w;
        v = *(const float4*)(kb + (size_t)(t0 + r) * DD + c);
        Kt[c+0][r] = v.x; Kt[c+1][r] = v.y; Kt[c+2][r] = v.z; Kt[c+3][r] = v.w;
        v = *(const float4*)(kb + (size_t)(t0 + r + 32) * DD + c);
        Kt[c+0][r+32] = v.x; Kt[c+1][r+32] = v.y; Kt[c+2][r+32] = v.z; Kt[c+3][r+32] = v.w;
    }
    __syncthreads();

    int g = tid >> 6, tl = tid & 63;
    unsigned long long acc2[8];
    #pragma unroll
    for (int j = 0; j < 8; j++) acc2[j] = 0ULL;

    #pragma unroll
    for (int d = 0; d < 32; d++) {
        float kv = Kt[d][tl];
        unsigned long long k2;
        DUP2(k2, kv);
        const unsigned long long* qp = (const unsigned long long*)&Qt[d][g * 16];
        #pragma unroll
        for (int j = 0; j < 8; j++) FMA2(acc2[j], qp[j], k2);
    }

    float* Sb = S + (size_t)bh * (LL * LL) + (size_t)l0 * LL + t0 + tl;
    #pragma unroll
    for (int j = 0; j < 8; j++) {
        float lo, hi;
        UNPACK2(lo, hi, acc2[j]);
        float s0 = lo * ATT_SCALE; s0 = (s0 > 0.f) ? s0 : 0.01f * s0;
        float s1 = hi * ATT_SCALE; s1 = (s1 > 0.f) ? s1 : 0.01f * s1;
        Sb[(size_t)(g * 16 + 2*j    ) * LL] = s0;
        Sb[(size_t)(g * 16 + 2*j + 1) * LL] = s1;
    }
}

// ---------------------------------------------------------------------------
// K3b: M[b,i,l,t] = mask( sum_h R[i,h]*S[b,h,l,t] ); full row max -> rmax.
// Block = (l, b); thread covers 4 t's for all 8 i.
// ---------------------------------------------------------------------------
__global__ __launch_bounds__(256) void mix_mask_kernel(
    const float* __restrict__ S, const float* __restrict__ adj,
    const float* __restrict__ R, float* __restrict__ M_out,
    float* __restrict__ rmax_out)
{
    __shared__ float Rs[64];
    __shared__ float red[8][8];
    int tid = threadIdx.x, lane = tid & 31, w = tid >> 5;
    int l = blockIdx.x, b = blockIdx.y;
    if (tid < 64) Rs[tid] = R[tid];
    __syncthreads();

    int t4 = tid * 4;
    float4 s[8];
    #pragma unroll
    for (int h = 0; h < 8; h++)
        s[h] = *(const float4*)(S + ((size_t)((b * 8 + h) * LL + l)) * LL + t4);

    float rmax[8];
    #pragma unroll
    for (int i = 0; i < 8; i++) {
        float mx = 0.f, my = 0.f, mz = 0.f, mw = 0.f;
        #pragma unroll
        for (int h = 0; h < 8; h++) {
            float r = Rs[i * 8 + h];
            mx += r * s[h].x; my += r * s[h].y;
            mz += r * s[h].z; mw += r * s[h].w;
        }
        size_t idx = ((size_t)((b * 8 + i) * LL + l)) * LL + t4;
        float4 a = *(const float4*)(adj + idx);
        float4 o;
        o.x = (a.x > 0.f) ? mx : -INFINITY;
        o.y = (a.y > 0.f) ? my : -INFINITY;
        o.z = (a.z > 0.f) ? mz : -INFINITY;
        o.w = (a.w > 0.f) ? mw : -INFINITY;
        *(float4*)(M_out + idx) = o;
        rmax[i] = fmaxf(fmaxf(o.x, o.y), fmaxf(o.z, o.w));
    }

    #pragma unroll
    for (int i = 0; i < 8; i++) {
        float mx = rmax[i];
        #pragma unroll
        for (int off = 16; off; off >>= 1)
            mx = fmaxf(mx, __shfl_down_sync(0xffffffffu, mx, off));
        if (lane == 0) red[w][i] = mx;
    }
    __syncthreads();
    if (tid < 8) {
        float mx = red[0][tid];
        #pragma unroll
        for (int ww = 1; ww < 8; ww++) mx = fmaxf(mx, red[ww][tid]);
        rmax_out[(b * 8 + tid) * LL + l] = mx;
    }
}

// ---------------------------------------------------------------------------
// K3c: rinv[row] = 1 / sum_t exp(M[row,t] - rmax[row])
// ---------------------------------------------------------------------------
__global__ __launch_bounds__(256) void rowsum_kernel(
    const float* __restrict__ M, const float* __restrict__ rmax,
    float* __restrict__ rinv)
{
    int row = blockIdx.x * 8 + (threadIdx.x >> 5);
    int lane = threadIdx.x & 31;
    const float* r = M + (size_t)row * LL;
    float mx = rmax[row];
    float sum = 0.f;
    #pragma unroll
    for (int j = 0; j < 8; j++) {
        float4 v = *(const float4*)(r + (j * 32 + lane) * 4);
        sum += __expf(v.x - mx) + __expf(v.y - mx)
             + __expf(v.z - mx) + __expf(v.w - mx);
    }
    #pragma unroll
    for (int off = 16; off; off >>= 1)
        sum += __shfl_down_sync(0xffffffffu, sum, off);
    if (lane == 0) rinv[row] = 1.f / sum;
}

// ---------------------------------------------------------------------------
// K4: normalize A in place + partial transposed-softmax column sums.
// ---------------------------------------------------------------------------
__global__ __launch_bounds__(256) void norm_colsum_kernel(
    float* __restrict__ A, const float* __restrict__ rmax,
    const float* __restrict__ rinv, float* __restrict__ pcol)
{
    int bi = blockIdx.y;
    int seg = blockIdx.z;
    int t = blockIdx.x * 256 + threadIdx.x;
    float* base = A + (size_t)bi * (LL * LL);
    const float* mx = rmax + bi * LL;
    const float* iv = rinv + bi * LL;

    int lr0 = seg * 256;
    float s0 = 0.f, s1 = 0.f, s2 = 0.f, s3 = 0.f;
    for (int lr = lr0; lr < lr0 + 256; lr += 4) {
        float m0 = base[(size_t)(lr + 0) * LL + t];
        float m1 = base[(size_t)(lr + 1) * LL + t];
        float m2 = base[(size_t)(lr + 2) * LL + t];
        float m3 = base[(size_t)(lr + 3) * LL + t];
        float a0 = __expf(m0 - mx[lr + 0]) * iv[lr + 0];
        float a1 = __expf(m1 - mx[lr + 1]) * iv[lr + 1];
        float a2 = __expf(m2 - mx[lr + 2]) * iv[lr + 2];
        float a3 = __expf(m3 - mx[lr + 3]) * iv[lr + 3];
        base[(size_t)(lr + 0) * LL + t] = a0;
        base[(size_t)(lr + 1) * LL + t] = a1;
        base[(size_t)(lr + 2) * LL + t] = a2;
        base[(size_t)(lr + 3) * LL + t] = a3;
        s0 += __expf(a0); s1 += __expf(a1);
        s2 += __expf(a2); s3 += __expf(a3);
    }
    pcol[(size_t)(seg * 32 + bi) * LL + t] = (s0 + s1) + (s2 + s3);
}

// ---------------------------------------------------------------------------
// K5: Ar[b,i,t,l] = exp(A[b,i,l,t]) / colsum(t)  (tiled transpose; 4 partials)
// ---------------------------------------------------------------------------
__global__ __launch_bounds__(256) void transpose_exp_kernel(
    const float* __restrict__ A, const float* __restrict__ pcol,
    float* __restrict__ Ar)
{
    __shared__ float Ts[32][33];
    int bi = blockIdx.z;
    int l0 = blockIdx.x * 32, t0 = blockIdx.y * 32;
    int lane = threadIdx.x & 31, wr = threadIdx.x >> 5;
    const float* base = A + (size_t)bi * (LL * LL);
    float* obase = Ar + (size_t)bi * (LL * LL);
    #pragma unroll
    for (int j = 0; j < 4; j++) {
        int lr = wr + j * 8;
        Ts[lr][lane] = base[(size_t)(l0 + lr) * LL + t0 + lane];
    }
    __syncthreads();
    #pragma unroll
    for (int j = 0; j < 4; j++) {
        int tr = wr + j * 8;
        int tt = t0 + tr;
        float rc = 1.f / (pcol[(size_t)(0 * 32 + bi) * LL + tt]
                        + pcol[(size_t)(1 * 32 + bi) * LL + tt]
                        + pcol[(size_t)(2 * 32 + bi) * LL + tt]
                        + pcol[(size_t)(3 * 32 + bi) * LL + tt]);
        obase[(size_t)tt * LL + l0 + lane] = __expf(Ts[lane][tr]) * rc;
    }
}

// ---------------------------------------------------------------------------
// K6: Out[r,n] = sum_m gelu(Vm[r,m]) * Wp[m,n], packed f32x2 inner loop.
// ---------------------------------------------------------------------------
__device__ __forceinline__ float gelu_exact(float v)
{
    return 0.5f * v * (1.f + erff(v * 0.70710678118654752f));
}

__global__ __launch_bounds__(256) void out_gemm(
    const float* __restrict__ V0, const float* __restrict__ V1,
    const float* __restrict__ Wp,
    float* __restrict__ O0, float* __restrict__ O1)
{
    __shared__ float Gs[32][68];
    __shared__ float Ws[1024];
    const float* Vm = blockIdx.z ? V1 : V0;
    float* Out = blockIdx.z ? O1 : O0;
    int tid = threadIdx.x;
    int r0 = blockIdx.x * 64, n0 = blockIdx.y * 32;
    int d = tid & 31, rg = tid >> 5;
    int rrow = tid >> 2, cseg = (tid & 3) * 8;

    unsigned long long acc2[4];
    #pragma unroll
    for (int j = 0; j < 4; j++) acc2[j] = 0ULL;

    for (int k0 = 0; k0 < DIMM; k0 += 32) {
        const float* vrow = Vm + (size_t)(r0 + rrow) * DIMM + k0 + cseg;
        float4 a0 = *(const float4*)(vrow);
        float4 a1 = *(const float4*)(vrow + 4);
        Gs[cseg+0][rrow] = gelu_exact(a0.x); Gs[cseg+1][rrow] = gelu_exact(a0.y);
        Gs[cseg+2][rrow] = gelu_exact(a0.z); Gs[cseg+3][rrow] = gelu_exact(a0.w);
        Gs[cseg+4][rrow] = gelu_exact(a1.x); Gs[cseg+5][rrow] = gelu_exact(a1.y);
        Gs[cseg+6][rrow] = gelu_exact(a1.z); Gs[cseg+7][rrow] = gelu_exact(a1.w);
        *(float4*)&Ws[(tid >> 3) * 32 + (tid & 7) * 4] =
            *(const float4*)(Wp + (size_t)(k0 + (tid >> 3)) * DIMM + n0 + (tid & 7) * 4);
        __syncthreads();

        #pragma unroll
        for (int kk = 0; kk < 32; kk++) {
            float bv = Ws[kk * 32 + d];
            unsigned long long bvv;
            DUP2(bvv, bv);
            const ulonglong2* gp = (const ulonglong2*)&Gs[kk][rg * 8];
            ulonglong2 g0 = gp[0];
            ulonglong2 g1 = gp[1];
            FMA2(acc2[0], g0.x, bvv); FMA2(acc2[1], g0.y, bvv);
            FMA2(acc2[2], g1.x, bvv); FMA2(acc2[3], g1.y, bvv);
        }
        __syncthreads();
    }
    #pragma unroll
    for (int j = 0; j < 4; j++) {
        float lo, hi;
        UNPACK2(lo, hi, acc2[j]);
        Out[(size_t)(r0 + rg * 8 + 2*j    ) * DIMM + n0 + d] = lo;
        Out[(size_t)(r0 + rg * 8 + 2*j + 1) * DIMM + n0 + d] = hi;
    }
}

// ---------------------------------------------------------------------------
// Launch. Output layout (float32, reference return order):
//   out [4,1024,256] | out_resize [4,1024,256] | A [4,8,1024,1024] | Ar [...]
// S (QK^T logits) borrows the Ar region: consumed by mix_mask before the
// transpose kernel writes Ar there.
// ---------------------------------------------------------------------------
extern "C" void kernel_launch(void* const* d_in, const int* in_sizes, int n_in,
                              void* d_out, int out_size)
{
    const float* x    = (const float*)d_in[0];
    const float* rx   = (const float*)d_in[1];
    const float* adj  = (const float*)d_in[2];
    const float* adjr = (const float*)d_in[3];
    const float* Wq   = (const float*)d_in[4];
    const float* Wk   = (const float*)d_in[5];
    const float* Wv   = (const float*)d_in[6];
    const float* R    = (const float*)d_in[7];
    const float* Wp   = (const float*)d_in[8];

    float* out  = (float*)d_out;
    float* outr = out + (size_t)BB * LL * DIMM;
    float* A    = out + (size_t)2 * BB * LL * DIMM;
    float* Ar   = A + (size_t)BB * HH * LL * LL;

    float* s = nullptr;
    cudaGetSymbolAddress((void**)&s, g_scratch);

    // K1: projections (xq, xk, xv, rv)
    proj_kernel<<<dim3(4096, 4), 256>>>(x, rx, Wq, Wk, Wv, s);

    // K2: q = adj @ xq ; k = adjr @ xk  -- sparse binary gather (exact)
    spmm_binary<<<dim3(128, 32, 2), 256>>>(adj,  s + OFF_XQ, s + OFF_Q,
                                           adjr, s + OFF_XK, s + OFF_K);

    // K3a: S = leaky(scale * q @ k^T)  -> Ar region (scratch use)
    qk_gemm<<<dim3(16, 16, 32), 256>>>(s + OFF_Q, s + OFF_K, Ar);

    // K3b: R-mix + mask -> raw M in A buffer; full row max
    mix_mask_kernel<<<dim3(1024, 4), 256>>>(Ar, adj, R, A, s + OFF_RMAXC);

    // K3c: row sums -> rinv
    rowsum_kernel<<<4096, 256>>>(A, s + OFF_RMAXC, s + OFF_RINV);

    // K4: normalize A in place + partial column sums (4 segments)
    norm_colsum_kernel<<<dim3(4, 32, 4), 256>>>(A, s + OFF_RMAXC, s + OFF_RINV,
                                                s + OFF_PCOL);

    // K5: dual softmax on transpose -> Ar (overwrites S scratch)
    transpose_exp_kernel<<<dim3(32, 32, 32), 256>>>(A, s + OFF_PCOL, Ar);

    // v = A @ xv  -- sparse weighted gather
    spmm_weighted<<<dim3(128, 32), 256>>>(A, s + OFF_XV, s + OFF_VM);

    // vr = Ar @ rv -- dense
    gemm_dense<<<dim3(16, 32), 256>>>(Ar, s + OFF_RV, s + OFF_VRM,
                                      (size_t)LL * DIMM, (size_t)DD, DIMM);

    // K6: out = gelu(v) @ Wp ; out_resize = gelu(vr) @ Wp
    out_gemm<<<dim3(64, 8, 2), 256>>>(s + OFF_VM, s + OFF_VRM, Wp, out, outr);
}

// round 10
// speedup vs baseline: 1.3469x; 1.0983x over previous
#include <cuda_runtime.h>
#include <math.h>

#define BB 4
#define HH 8
#define LL 1024
#define DD 32
#define DIMM 256
#define ATT_SCALE 0.0625f   // DIM^-0.5 = 1/16

#define M1 1048576
// scratch layout (floats)
#define OFF_XQ  (0*M1)
#define OFF_XK  (1*M1)
#define OFF_XV  (2*M1)
#define OFF_RV  (3*M1)
#define OFF_Q   (4*M1)
#define OFF_K   (5*M1)
#define OFF_VM  (6*M1)
#define OFF_VRM (7*M1)
#define OFF_PCOL  (8*M1)                    // 4 segs x 32 bi x 1024 t = 131072
#define OFF_RMAXC (8*M1 + 131072)           // full row max, 32768
#define OFF_RINV  (8*M1 + 163840)           // 32768

__device__ float g_scratch[8*M1 + 196608];

// packed fp32x2 helpers (sm_100+)
#define FMA2(acc, a, b) \
    asm("fma.rn.f32x2 %0, %1, %2, %0;" : "+l"(acc) : "l"(a), "l"(b))
#define DUP2(dst, v) \
    asm("mov.b64 %0, {%1, %1};" : "=l"(dst) : "f"(v))
#define UNPACK2(lo, hi, v) \
    asm("mov.b64 {%0, %1}, %2;" : "=f"(lo), "=f"(hi) : "l"(v))

// ---------------------------------------------------------------------------
// K1: per-head projections  dst[b,h,t,d] = sum_dp src[b,t,h*32+dp] * W[dp,d]
// ---------------------------------------------------------------------------
__global__ __launch_bounds__(256) void proj_kernel(
    const float* __restrict__ x, const float* __restrict__ rx,
    const float* __restrict__ Wq, const float* __restrict__ Wk,
    const float* __restrict__ Wv, float* __restrict__ scratch)
{
    int tid = threadIdx.x;
    int which = blockIdx.y;
    const float* src = (which == 0 || which == 2) ? x : rx;
    const float* W = (which == 0) ? Wq : ((which == 1) ? Wk : Wv);
    float* dst = scratch + (size_t)which * M1;

    __shared__ float Ws[1024];
    __shared__ float Xs[8][32];
    for (int i = tid; i < 1024; i += 256) Ws[i] = W[i];

    int r = blockIdx.x * 8 + (tid >> 5);   // r = (b*8+h)*1024 + t
    int d = tid & 31;
    int b = r >> 13;
    int h = (r >> 10) & 7;
    int t = r & 1023;
    Xs[tid >> 5][d] = src[((size_t)(b * LL + t)) * DIMM + h * 32 + d];
    __syncthreads();

    float acc = 0.f;
    #pragma unroll
    for (int dp = 0; dp < 32; dp++) acc += Xs[tid >> 5][dp] * Ws[dp * 32 + d];
    dst[(size_t)r * 32 + d] = acc;
}

// ---------------------------------------------------------------------------
// K2: SPARSE binary gather-sum:  O[bh][l][d] = sum_{t: G[bh][l][t] > 0} X[bh][t][d]
// ---------------------------------------------------------------------------
__global__ __launch_bounds__(256) void spmm_binary(
    const float* __restrict__ G0, const float* __restrict__ X0, float* __restrict__ O0,
    const float* __restrict__ G1, const float* __restrict__ X1, float* __restrict__ O1)
{
    int lane = threadIdx.x & 31, w = threadIdx.x >> 5;
    int l = blockIdx.x * 8 + w;
    int bh = blockIdx.y;
    const float* G = (blockIdx.z ? G1 : G0) + (size_t)bh * (LL * LL) + (size_t)l * LL;
    const float* X = (blockIdx.z ? X1 : X0) + (size_t)bh * (LL * DD);
    float* O = (blockIdx.z ? O1 : O0) + (size_t)bh * (LL * DD);

    float acc0 = 0.f, acc1 = 0.f;
    for (int t0 = 0; t0 < LL; t0 += 128) {
        float4 g = *(const float4*)&G[t0 + lane * 4];
        #pragma unroll
        for (int c = 0; c < 4; c++) {
            float gv = (c == 0) ? g.x : (c == 1) ? g.y : (c == 2) ? g.z : g.w;
            unsigned m = __ballot_sync(0xffffffffu, gv > 0.f);
            while (m) {
                int j = __ffs(m) - 1; m &= m - 1;
                acc0 += X[(t0 + j * 4 + c) * DD + lane];
                if (m) {
                    j = __ffs(m) - 1; m &= m - 1;
                    acc1 += X[(t0 + j * 4 + c) * DD + lane];
                }
            }
        }
    }
    O[(size_t)l * DD + lane] = acc0 + acc1;
}

// ---------------------------------------------------------------------------
// K2b: SPARSE weighted gather:  VM[b,l,h*32+d] = sum_{t: A[bh][l][t] > 0} A*X
// ---------------------------------------------------------------------------
__global__ __launch_bounds__(256) void spmm_weighted(
    const float* __restrict__ A, const float* __restrict__ X, float* __restrict__ O)
{
    int lane = threadIdx.x & 31, w = threadIdx.x >> 5;
    int l = blockIdx.x * 8 + w;
    int bh = blockIdx.y;
    int b = bh >> 3, h = bh & 7;
    const float* G = A + (size_t)bh * (LL * LL) + (size_t)l * LL;
    const float* Xb = X + (size_t)bh * (LL * DD);

    float acc0 = 0.f, acc1 = 0.f;
    for (int t0 = 0; t0 < LL; t0 += 128) {
        float4 g = *(const float4*)&G[t0 + lane * 4];
        #pragma unroll
        for (int c = 0; c < 4; c++) {
            float gv = (c == 0) ? g.x : (c == 1) ? g.y : (c == 2) ? g.z : g.w;
            unsigned m = __ballot_sync(0xffffffffu, gv > 0.f);
            while (m) {
                int j = __ffs(m) - 1; m &= m - 1;
                float av = __shfl_sync(0xffffffffu, gv, j);
                acc0 += av * Xb[(t0 + j * 4 + c) * DD + lane];
                if (m) {
                    j = __ffs(m) - 1; m &= m - 1;
                    float av2 = __shfl_sync(0xffffffffu, gv, j);
                    acc1 += av2 * Xb[(t0 + j * 4 + c) * DD + lane];
                }
            }
        }
    }
    O[(size_t)b * (LL * DIMM) + (size_t)l * DIMM + h * 32 + lane] = acc0 + acc1;
}

// ---------------------------------------------------------------------------
// K2c: DENSE per-(b,h) SGEMM (vr = Ar @ rv). 128x32 tile, 4x4 thread tile
// (2.0 B smem / MAC), packed f32x2, register prefetch.
// ---------------------------------------------------------------------------
__global__ __launch_bounds__(256) void gemm_dense(
    const float* __restrict__ Amat, const float* __restrict__ Bm,
    float* __restrict__ C, size_t c_b_stride, size_t c_h_stride, int c_row_stride)
{
    __shared__ float Ast[32][132];   // [k][row]
    __shared__ float Bs[32][32];     // [k][d]

    int tid = threadIdx.x;
    int bh = blockIdx.y;
    const float* A  = Amat + (size_t)bh * (LL * LL);
    const float* Bb = Bm + (size_t)bh * (LL * DD);
    float* Cb = C + (size_t)(bh >> 3) * c_b_stride + (size_t)(bh & 7) * c_h_stride;
    int l0 = blockIdx.x * 128;

    int lrow = tid >> 1, cseg = (tid & 1) * 16;   // staging
    int brow = tid >> 3, bcol = (tid & 7) * 4;    // B staging
    int rg4 = (tid >> 3) * 4;                     // 4 rows rg4..rg4+3
    int cg  = (tid & 7) * 4;                      // 4 cols cg..cg+3

    unsigned long long acc2[4][2];
    #pragma unroll
    for (int c4 = 0; c4 < 4; c4++) { acc2[c4][0] = 0ULL; acc2[c4][1] = 0ULL; }

    float4 pa0, pa1, pa2, pa3, pb;
    {
        const float* p = A + (size_t)(l0 + lrow) * LL + cseg;
        pa0 = *(const float4*)(p);      pa1 = *(const float4*)(p + 4);
        pa2 = *(const float4*)(p + 8);  pa3 = *(const float4*)(p + 12);
        pb  = *(const float4*)(Bb + (size_t)brow * DD + bcol);
    }

    for (int c = 0; c < 32; c++) {
        Ast[cseg+ 0][lrow]=pa0.x; Ast[cseg+ 1][lrow]=pa0.y;
        Ast[cseg+ 2][lrow]=pa0.z; Ast[cseg+ 3][lrow]=pa0.w;
        Ast[cseg+ 4][lrow]=pa1.x; Ast[cseg+ 5][lrow]=pa1.y;
        Ast[cseg+ 6][lrow]=pa1.z; Ast[cseg+ 7][lrow]=pa1.w;
        Ast[cseg+ 8][lrow]=pa2.x; Ast[cseg+ 9][lrow]=pa2.y;
        Ast[cseg+10][lrow]=pa2.z; Ast[cseg+11][lrow]=pa2.w;
        Ast[cseg+12][lrow]=pa3.x; Ast[cseg+13][lrow]=pa3.y;
        Ast[cseg+14][lrow]=pa3.z; Ast[cseg+15][lrow]=pa3.w;
        *(float4*)&Bs[brow][bcol] = pb;
        __syncthreads();

        if (c < 31) {
            int k0 = (c + 1) * 32;
            const float* p = A + (size_t)(l0 + lrow) * LL + k0 + cseg;
            pa0 = *(const float4*)(p);      pa1 = *(const float4*)(p + 4);
            pa2 = *(const float4*)(p + 8);  pa3 = *(const float4*)(p + 12);
            pb  = *(const float4*)(Bb + (size_t)(k0 + brow) * DD + bcol);
        }

        #pragma unroll
        for (int kk = 0; kk < 32; kk++) {
            ulonglong2 ap = *(const ulonglong2*)&Ast[kk][rg4];
            float4 bv = *(const float4*)&Bs[kk][cg];
            const float bl[4] = {bv.x, bv.y, bv.z, bv.w};
            #pragma unroll
            for (int c4 = 0; c4 < 4; c4++) {
                unsigned long long b2;
                DUP2(b2, bl[c4]);
                FMA2(acc2[c4][0], ap.x, b2);
                FMA2(acc2[c4][1], ap.y, b2);
            }
        }
        __syncthreads();
    }

    #pragma unroll
    for (int r = 0; r < 4; r++) {
        float4 o;
        #pragma unroll
        for (int c4 = 0; c4 < 4; c4++) {
            float lo, hi;
            UNPACK2(lo, hi, acc2[c4][r >> 1]);
            ((float*)&o)[c4] = (r & 1) ? hi : lo;
        }
        *(float4*)(Cb + (size_t)(l0 + rg4 + r) * c_row_stride + cg) = o;
    }
}

// ---------------------------------------------------------------------------
// K3a: S[bh][l][t] = leaky(ATT_SCALE * dot(q[bh][l], k[bh][t]))
// 64x64 tile, 4l x 4t per thread (2.0 B smem / MAC), packed FMA.
// ---------------------------------------------------------------------------
__global__ __launch_bounds__(256) void qk_gemm(
    const float* __restrict__ q, const float* __restrict__ k,
    float* __restrict__ S)
{
    __shared__ float Qt[32][68];   // [d][l]
    __shared__ float Kt[32][68];   // [d][t]

    int tid = threadIdx.x;
    int bh = blockIdx.z;
    int t0 = blockIdx.x * 64, l0 = blockIdx.y * 64;
    const float* qb = q + (size_t)bh * (LL * DD);
    const float* kb = k + (size_t)bh * (LL * DD);

    {
        int r = tid >> 3, c = (tid & 7) * 4;
        float4 v;
        v = *(const float4*)(qb + (size_t)(l0 + r) * DD + c);
        Qt[c+0][r] = v.x; Qt[c+1][r] = v.y; Qt[c+2][r] = v.z; Qt[c+3][r] = v.w;
        v = *(const float4*)(qb + (size_t)(l0 + r + 32) * DD + c);
        Qt[c+0][r+32] = v.x; Qt[c+1][r+32] = v.y; Qt[c+2][r+32] = v.z; Qt[c+3][r+32] = v.w;
        v = *(const float4*)(kb + (size_t)(t0 + r) * DD + c);
        Kt[c+0][r] = v.x; Kt[c+1][r] = v.y; Kt[c+2][r] = v.z; Kt[c+3][r] = v.w;
        v = *(const float4*)(kb + (size_t)(t0 + r + 32) * DD + c);
        Kt[c+0][r+32] = v.x; Kt[c+1][r+32] = v.y; Kt[c+2][r+32] = v.z; Kt[c+3][r+32] = v.w;
    }
    __syncthreads();

    int lg = (tid >> 4) * 4;   // 4 l rows
    int tg = (tid & 15) * 4;   // 4 t cols
    unsigned long long acc2[4][2];   // [t][l-pair]
    #pragma unroll
    for (int t = 0; t < 4; t++) { acc2[t][0] = 0ULL; acc2[t][1] = 0ULL; }

    #pragma unroll
    for (int d = 0; d < 32; d++) {
        ulonglong2 qp = *(const ulonglong2*)&Qt[d][lg];
        float4 kv = *(const float4*)&Kt[d][tg];
        const float kl[4] = {kv.x, kv.y, kv.z, kv.w};
        #pragma unroll
        for (int t = 0; t < 4; t++) {
            unsigned long long k2;
            DUP2(k2, kl[t]);
            FMA2(acc2[t][0], qp.x, k2);
            FMA2(acc2[t][1], qp.y, k2);
        }
    }

    float* Sb = S + (size_t)bh * (LL * LL);
    #pragma unroll
    for (int ll = 0; ll < 4; ll++) {
        float4 o;
        #pragma unroll
        for (int t = 0; t < 4; t++) {
            float lo, hi;
            UNPACK2(lo, hi, acc2[t][ll >> 1]);
            float val = ((ll & 1) ? hi : lo) * ATT_SCALE;
            ((float*)&o)[t] = (val > 0.f) ? val : 0.01f * val;
        }
        *(float4*)(Sb + (size_t)(l0 + lg + ll) * LL + t0 + tg) = o;
    }
}

// ---------------------------------------------------------------------------
// K3b: M[b,i,l,t] = mask( sum_h R[i,h]*S[b,h,l,t] ); full row max -> rmax.
// ---------------------------------------------------------------------------
__global__ __launch_bounds__(256) void mix_mask_kernel(
    const float* __restrict__ S, const float* __restrict__ adj,
    const float* __restrict__ R, float* __restrict__ M_out,
    float* __restrict__ rmax_out)
{
    __shared__ float Rs[64];
    __shared__ float red[8][8];
    int tid = threadIdx.x, lane = tid & 31, w = tid >> 5;
    int l = blockIdx.x, b = blockIdx.y;
    if (tid < 64) Rs[tid] = R[tid];
    __syncthreads();

    int t4 = tid * 4;
    float4 s[8];
    #pragma unroll
    for (int h = 0; h < 8; h++)
        s[h] = *(const float4*)(S + ((size_t)((b * 8 + h) * LL + l)) * LL + t4);

    float rmax[8];
    #pragma unroll
    for (int i = 0; i < 8; i++) {
        float mx = 0.f, my = 0.f, mz = 0.f, mw = 0.f;
        #pragma unroll
        for (int h = 0; h < 8; h++) {
            float r = Rs[i * 8 + h];
            mx += r * s[h].x; my += r * s[h].y;
            mz += r * s[h].z; mw += r * s[h].w;
        }
        size_t idx = ((size_t)((b * 8 + i) * LL + l)) * LL + t4;
        float4 a = *(const float4*)(adj + idx);
        float4 o;
        o.x = (a.x > 0.f) ? mx : -INFINITY;
        o.y = (a.y > 0.f) ? my : -INFINITY;
        o.z = (a.z > 0.f) ? mz : -INFINITY;
        o.w = (a.w > 0.f) ? mw : -INFINITY;
        *(float4*)(M_out + idx) = o;
        rmax[i] = fmaxf(fmaxf(o.x, o.y), fmaxf(o.z, o.w));
    }

    #pragma unroll
    for (int i = 0; i < 8; i++) {
        float mx = rmax[i];
        #pragma unroll
        for (int off = 16; off; off >>= 1)
            mx = fmaxf(mx, __shfl_down_sync(0xffffffffu, mx, off));
        if (lane == 0) red[w][i] = mx;
    }
    __syncthreads();
    if (tid < 8) {
        float mx = red[0][tid];
        #pragma unroll
        for (int ww = 1; ww < 8; ww++) mx = fmaxf(mx, red[ww][tid]);
        rmax_out[(b * 8 + tid) * LL + l] = mx;
    }
}

// ---------------------------------------------------------------------------
// K3c: rinv[row] = 1 / sum_t exp(M[row,t] - rmax[row])
// ---------------------------------------------------------------------------
__global__ __launch_bounds__(256) void rowsum_kernel(
    const float* __restrict__ M, const float* __restrict__ rmax,
    float* __restrict__ rinv)
{
    int row = blockIdx.x * 8 + (threadIdx.x >> 5);
    int lane = threadIdx.x & 31;
    const float* r = M + (size_t)row * LL;
    float mx = rmax[row];
    float sum = 0.f;
    #pragma unroll
    for (int j = 0; j < 8; j++) {
        float4 v = *(const float4*)(r + (j * 32 + lane) * 4);
        sum += __expf(v.x - mx) + __expf(v.y - mx)
             + __expf(v.z - mx) + __expf(v.w - mx);
    }
    #pragma unroll
    for (int off = 16; off; off >>= 1)
        sum += __shfl_down_sync(0xffffffffu, sum, off);
    if (lane == 0) rinv[row] = 1.f / sum;
}

// ---------------------------------------------------------------------------
// K4: normalize A in place + partial transposed-softmax column sums.
// ---------------------------------------------------------------------------
__global__ __launch_bounds__(256) void norm_colsum_kernel(
    float* __restrict__ A, const float* __restrict__ rmax,
    const float* __restrict__ rinv, float* __restrict__ pcol)
{
    int bi = blockIdx.y;
    int seg = blockIdx.z;
    int t = blockIdx.x * 256 + threadIdx.x;
    float* base = A + (size_t)bi * (LL * LL);
    const float* mx = rmax + bi * LL;
    const float* iv = rinv + bi * LL;

    int lr0 = seg * 256;
    float s0 = 0.f, s1 = 0.f, s2 = 0.f, s3 = 0.f;
    for (int lr = lr0; lr < lr0 + 256; lr += 4) {
        float m0 = base[(size_t)(lr + 0) * LL + t];
        float m1 = base[(size_t)(lr + 1) * LL + t];
        float m2 = base[(size_t)(lr + 2) * LL + t];
        float m3 = base[(size_t)(lr + 3) * LL + t];
        float a0 = __expf(m0 - mx[lr + 0]) * iv[lr + 0];
        float a1 = __expf(m1 - mx[lr + 1]) * iv[lr + 1];
        float a2 = __expf(m2 - mx[lr + 2]) * iv[lr + 2];
        float a3 = __expf(m3 - mx[lr + 3]) * iv[lr + 3];
        base[(size_t)(lr + 0) * LL + t] = a0;
        base[(size_t)(lr + 1) * LL + t] = a1;
        base[(size_t)(lr + 2) * LL + t] = a2;
        base[(size_t)(lr + 3) * LL + t] = a3;
        s0 += __expf(a0); s1 += __expf(a1);
        s2 += __expf(a2); s3 += __expf(a3);
    }
    pcol[(size_t)(seg * 32 + bi) * LL + t] = (s0 + s1) + (s2 + s3);
}

// ---------------------------------------------------------------------------
// K5: Ar[b,i,t,l] = exp(A[b,i,l,t]) / colsum(t)  (tiled transpose; 4 partials)
// ---------------------------------------------------------------------------
__global__ __launch_bounds__(256) void transpose_exp_kernel(
    const float* __restrict__ A, const float* __restrict__ pcol,
    float* __restrict__ Ar)
{
    __shared__ float Ts[32][33];
    int bi = blockIdx.z;
    int l0 = blockIdx.x * 32, t0 = blockIdx.y * 32;
    int lane = threadIdx.x & 31, wr = threadIdx.x >> 5;
    const float* base = A + (size_t)bi * (LL * LL);
    float* obase = Ar + (size_t)bi * (LL * LL);
    #pragma unroll
    for (int j = 0; j < 4; j++) {
        int lr = wr + j * 8;
        Ts[lr][lane] = base[(size_t)(l0 + lr) * LL + t0 + lane];
    }
    __syncthreads();
    #pragma unroll
    for (int j = 0; j < 4; j++) {
        int tr = wr + j * 8;
        int tt = t0 + tr;
        float rc = 1.f / (pcol[(size_t)(0 * 32 + bi) * LL + tt]
                        + pcol[(size_t)(1 * 32 + bi) * LL + tt]
                        + pcol[(size_t)(2 * 32 + bi) * LL + tt]
                        + pcol[(size_t)(3 * 32 + bi) * LL + tt]);
        obase[(size_t)tt * LL + l0 + lane] = __expf(Ts[lane][tr]) * rc;
    }
}

// ---------------------------------------------------------------------------
// K6: Out[r,n] = sum_m gelu(Vm[r,m]) * Wp[m,n]. 128x32 tile, 4x4 thread tile.
// ---------------------------------------------------------------------------
__device__ __forceinline__ float gelu_exact(float v)
{
    return 0.5f * v * (1.f + erff(v * 0.70710678118654752f));
}

__global__ __launch_bounds__(256) void out_gemm(
    const float* __restrict__ V0, const float* __restrict__ V1,
    const float* __restrict__ Wp,
    float* __restrict__ O0, float* __restrict__ O1)
{
    __shared__ float Gs[32][132];   // [k][row], gelu'd
    __shared__ float Ws[32][32];    // [k][n]
    const float* Vm = blockIdx.z ? V1 : V0;
    float* Out = blockIdx.z ? O1 : O0;
    int tid = threadIdx.x;
    int r0 = blockIdx.x * 128, n0 = blockIdx.y * 32;

    int lrow = tid >> 1, cseg = (tid & 1) * 16;
    int brow = tid >> 3, bcol = (tid & 7) * 4;
    int rg4 = (tid >> 3) * 4;
    int cg  = (tid & 7) * 4;

    unsigned long long acc2[4][2];
    #pragma unroll
    for (int c4 = 0; c4 < 4; c4++) { acc2[c4][0] = 0ULL; acc2[c4][1] = 0ULL; }

    for (int k0 = 0; k0 < DIMM; k0 += 32) {
        const float* vrow = Vm + (size_t)(r0 + lrow) * DIMM + k0 + cseg;
        float4 a0 = *(const float4*)(vrow);
        float4 a1 = *(const float4*)(vrow + 4);
        float4 a2 = *(const float4*)(vrow + 8);
        float4 a3 = *(const float4*)(vrow + 12);
        Gs[cseg+ 0][lrow]=gelu_exact(a0.x); Gs[cseg+ 1][lrow]=gelu_exact(a0.y);
        Gs[cseg+ 2][lrow]=gelu_exact(a0.z); Gs[cseg+ 3][lrow]=gelu_exact(a0.w);
        Gs[cseg+ 4][lrow]=gelu_exact(a1.x); Gs[cseg+ 5][lrow]=gelu_exact(a1.y);
        Gs[cseg+ 6][lrow]=gelu_exact(a1.z); Gs[cseg+ 7][lrow]=gelu_exact(a1.w);
        Gs[cseg+ 8][lrow]=gelu_exact(a2.x); Gs[cseg+ 9][lrow]=gelu_exact(a2.y);
        Gs[cseg+10][lrow]=gelu_exact(a2.z); Gs[cseg+11][lrow]=gelu_exact(a2.w);
        Gs[cseg+12][lrow]=gelu_exact(a3.x); Gs[cseg+13][lrow]=gelu_exact(a3.y);
        Gs[cseg+14][lrow]=gelu_exact(a3.z); Gs[cseg+15][lrow]=gelu_exact(a3.w);
        *(float4*)&Ws[brow][bcol] =
            *(const float4*)(Wp + (size_t)(k0 + brow) * DIMM + n0 + bcol);
        __syncthreads();

        #pragma unroll
        for (int kk = 0; kk < 32; kk++) {
            ulonglong2 ap = *(const ulonglong2*)&Gs[kk][rg4];
            float4 bv = *(const float4*)&Ws[kk][cg];
            const float bl[4] = {bv.x, bv.y, bv.z, bv.w};
            #pragma unroll
            for (int c4 = 0; c4 < 4; c4++) {
                unsigned long long b2;
                DUP2(b2, bl[c4]);
                FMA2(acc2[c4][0], ap.x, b2);
                FMA2(acc2[c4][1], ap.y, b2);
            }
        }
        __syncthreads();
    }

    #pragma unroll
    for (int r = 0; r < 4; r++) {
        float4 o;
        #pragma unroll
        for (int c4 = 0; c4 < 4; c4++) {
            float lo, hi;
            UNPACK2(lo, hi, acc2[c4][r >> 1]);
            ((float*)&o)[c4] = (r & 1) ? hi : lo;
        }
        *(float4*)(Out + (size_t)(r0 + rg4 + r) * DIMM + n0 + cg) = o;
    }
}

// ---------------------------------------------------------------------------
// Launch. Output layout (float32, reference return order):
//   out [4,1024,256] | out_resize [4,1024,256] | A [4,8,1024,1024] | Ar [...]
// S (QK^T logits) borrows the Ar region until transpose overwrites it.
// ---------------------------------------------------------------------------
extern "C" void kernel_launch(void* const* d_in, const int* in_sizes, int n_in,
                              void* d_out, int out_size)
{
    const float* x    = (const float*)d_in[0];
    const float* rx   = (const float*)d_in[1];
    const float* adj  = (const float*)d_in[2];
    const float* adjr = (const float*)d_in[3];
    const float* Wq   = (const float*)d_in[4];
    const float* Wk   = (const float*)d_in[5];
    const float* Wv   = (const float*)d_in[6];
    const float* R    = (const float*)d_in[7];
    const float* Wp   = (const float*)d_in[8];

    float* out  = (float*)d_out;
    float* outr = out + (size_t)BB * LL * DIMM;
    float* A    = out + (size_t)2 * BB * LL * DIMM;
    float* Ar   = A + (size_t)BB * HH * LL * LL;

    float* s = nullptr;
    cudaGetSymbolAddress((void**)&s, g_scratch);

    // K1: projections (xq, xk, xv, rv)
    proj_kernel<<<dim3(4096, 4), 256>>>(x, rx, Wq, Wk, Wv, s);

    // K2: q = adj @ xq ; k = adjr @ xk  -- sparse binary gather (exact)
    spmm_binary<<<dim3(128, 32, 2), 256>>>(adj,  s + OFF_XQ, s + OFF_Q,
                                           adjr, s + OFF_XK, s + OFF_K);

    // K3a: S = leaky(scale * q @ k^T)  -> Ar region (scratch use)
    qk_gemm<<<dim3(16, 16, 32), 256>>>(s + OFF_Q, s + OFF_K, Ar);

    // K3b: R-mix + mask -> raw M in A buffer; full row max
    mix_mask_kernel<<<dim3(1024, 4), 256>>>(Ar, adj, R, A, s + OFF_RMAXC);

    // K3c: row sums -> rinv
    rowsum_kernel<<<4096, 256>>>(A, s + OFF_RMAXC, s + OFF_RINV);

    // K4: normalize A in place + partial column sums (4 segments)
    norm_colsum_kernel<<<dim3(4, 32, 4), 256>>>(A, s + OFF_RMAXC, s + OFF_RINV,
                                                s + OFF_PCOL);

    // K5: dual softmax on transpose -> Ar (overwrites S scratch)
    transpose_exp_kernel<<<dim3(32, 32, 32), 256>>>(A, s + OFF_PCOL, Ar);

    // v = A @ xv  -- sparse weighted gather
    spmm_weighted<<<dim3(128, 32), 256>>>(A, s + OFF_XV, s + OFF_VM);

    // vr = Ar @ rv -- dense
    gemm_dense<<<dim3(8, 32), 256>>>(Ar, s + OFF_RV, s + OFF_VRM,
                                     (size_t)LL * DIMM, (size_t)DD, DIMM);

    // K6: out = gelu(v) @ Wp ; out_resize = gelu(vr) @ Wp
    out_gemm<<<dim3(32, 8, 2), 256>>>(s + OFF_VM, s + OFF_VRM, Wp, out, outr);
}

// round 11
// speedup vs baseline: 1.5117x; 1.1223x over previous
#include <cuda_runtime.h>
#include <math.h>

#define BB 4
#define HH 8
#define LL 1024
#define DD 32
#define DIMM 256
#define ATT_SCALE 0.0625f   // DIM^-0.5 = 1/16

#define M1 1048576
// scratch layout (floats)
#define OFF_XQ  (0*M1)
#define OFF_XK  (1*M1)
#define OFF_XV  (2*M1)
#define OFF_RV  (3*M1)
#define OFF_Q   (4*M1)
#define OFF_K   (5*M1)
#define OFF_VM  (6*M1)
#define OFF_VRM (7*M1)
#define OFF_PCOL  (8*M1)                    // 4 segs x 32 bi x 1024 t = 131072

__device__ float g_scratch[8*M1 + 131072];

// packed fp32x2 helpers (sm_100+)
#define FMA2(acc, a, b) \
    asm("fma.rn.f32x2 %0, %1, %2, %0;" : "+l"(acc) : "l"(a), "l"(b))
#define DUP2(dst, v) \
    asm("mov.b64 %0, {%1, %1};" : "=l"(dst) : "f"(v))
#define UNPACK2(lo, hi, v) \
    asm("mov.b64 {%0, %1}, %2;" : "=f"(lo), "=f"(hi) : "l"(v))

// ---------------------------------------------------------------------------
// K1: per-head projections  dst[b,h,t,d] = sum_dp src[b,t,h*32+dp] * W[dp,d]
// ---------------------------------------------------------------------------
__global__ __launch_bounds__(256) void proj_kernel(
    const float* __restrict__ x, const float* __restrict__ rx,
    const float* __restrict__ Wq, const float* __restrict__ Wk,
    const float* __restrict__ Wv, float* __restrict__ scratch)
{
    int tid = threadIdx.x;
    int which = blockIdx.y;
    const float* src = (which == 0 || which == 2) ? x : rx;
    const float* W = (which == 0) ? Wq : ((which == 1) ? Wk : Wv);
    float* dst = scratch + (size_t)which * M1;

    __shared__ float Ws[1024];
    __shared__ float Xs[8][32];
    for (int i = tid; i < 1024; i += 256) Ws[i] = W[i];

    int r = blockIdx.x * 8 + (tid >> 5);   // r = (b*8+h)*1024 + t
    int d = tid & 31;
    int b = r >> 13;
    int h = (r >> 10) & 7;
    int t = r & 1023;
    Xs[tid >> 5][d] = src[((size_t)(b * LL + t)) * DIMM + h * 32 + d];
    __syncthreads();

    float acc = 0.f;
    #pragma unroll
    for (int dp = 0; dp < 32; dp++) acc += Xs[tid >> 5][dp] * Ws[dp * 32 + d];
    dst[(size_t)r * 32 + d] = acc;
}

// ---------------------------------------------------------------------------
// K2: SPARSE binary gather-sum:  O[bh][l][d] = sum_{t: G[bh][l][t] > 0} X[bh][t][d]
// ---------------------------------------------------------------------------
__global__ __launch_bounds__(256) void spmm_binary(
    const float* __restrict__ G0, const float* __restrict__ X0, float* __restrict__ O0,
    const float* __restrict__ G1, const float* __restrict__ X1, float* __restrict__ O1)
{
    int lane = threadIdx.x & 31, w = threadIdx.x >> 5;
    int l = blockIdx.x * 8 + w;
    int bh = blockIdx.y;
    const float* G = (blockIdx.z ? G1 : G0) + (size_t)bh * (LL * LL) + (size_t)l * LL;
    const float* X = (blockIdx.z ? X1 : X0) + (size_t)bh * (LL * DD);
    float* O = (blockIdx.z ? O1 : O0) + (size_t)bh * (LL * DD);

    float acc0 = 0.f, acc1 = 0.f;
    for (int t0 = 0; t0 < LL; t0 += 128) {
        float4 g = *(const float4*)&G[t0 + lane * 4];
        #pragma unroll
        for (int c = 0; c < 4; c++) {
            float gv = (c == 0) ? g.x : (c == 1) ? g.y : (c == 2) ? g.z : g.w;
            unsigned m = __ballot_sync(0xffffffffu, gv > 0.f);
            while (m) {
                int j = __ffs(m) - 1; m &= m - 1;
                acc0 += X[(t0 + j * 4 + c) * DD + lane];
                if (m) {
                    j = __ffs(m) - 1; m &= m - 1;
                    acc1 += X[(t0 + j * 4 + c) * DD + lane];
                }
            }
        }
    }
    O[(size_t)l * DD + lane] = acc0 + acc1;
}

// ---------------------------------------------------------------------------
// K2b: SPARSE weighted gather:  VM[b,l,h*32+d] = sum_{t: A[bh][l][t] > 0} A*X
// ---------------------------------------------------------------------------
__global__ __launch_bounds__(256) void spmm_weighted(
    const float* __restrict__ A, const float* __restrict__ X, float* __restrict__ O)
{
    int lane = threadIdx.x & 31, w = threadIdx.x >> 5;
    int l = blockIdx.x * 8 + w;
    int bh = blockIdx.y;
    int b = bh >> 3, h = bh & 7;
    const float* G = A + (size_t)bh * (LL * LL) + (size_t)l * LL;
    const float* Xb = X + (size_t)bh * (LL * DD);

    float acc0 = 0.f, acc1 = 0.f;
    for (int t0 = 0; t0 < LL; t0 += 128) {
        float4 g = *(const float4*)&G[t0 + lane * 4];
        #pragma unroll
        for (int c = 0; c < 4; c++) {
            float gv = (c == 0) ? g.x : (c == 1) ? g.y : (c == 2) ? g.z : g.w;
            unsigned m = __ballot_sync(0xffffffffu, gv > 0.f);
            while (m) {
                int j = __ffs(m) - 1; m &= m - 1;
                float av = __shfl_sync(0xffffffffu, gv, j);
                acc0 += av * Xb[(t0 + j * 4 + c) * DD + lane];
                if (m) {
                    j = __ffs(m) - 1; m &= m - 1;
                    float av2 = __shfl_sync(0xffffffffu, gv, j);
                    acc1 += av2 * Xb[(t0 + j * 4 + c) * DD + lane];
                }
            }
        }
    }
    O[(size_t)b * (LL * DIMM) + (size_t)l * DIMM + h * 32 + lane] = acc0 + acc1;
}

// ---------------------------------------------------------------------------
// K2c: DENSE per-(b,h) SGEMM (vr = Ar @ rv). 128x32 tile, 4x4 thread tile.
// ---------------------------------------------------------------------------
__global__ __launch_bounds__(256) void gemm_dense(
    const float* __restrict__ Amat, const float* __restrict__ Bm,
    float* __restrict__ C, size_t c_b_stride, size_t c_h_stride, int c_row_stride)
{
    __shared__ float Ast[32][132];   // [k][row]
    __shared__ float Bs[32][32];     // [k][d]

    int tid = threadIdx.x;
    int bh = blockIdx.y;
    const float* A  = Amat + (size_t)bh * (LL * LL);
    const float* Bb = Bm + (size_t)bh * (LL * DD);
    float* Cb = C + (size_t)(bh >> 3) * c_b_stride + (size_t)(bh & 7) * c_h_stride;
    int l0 = blockIdx.x * 128;

    int lrow = tid >> 1, cseg = (tid & 1) * 16;   // staging
    int brow = tid >> 3, bcol = (tid & 7) * 4;    // B staging
    int rg4 = (tid >> 3) * 4;                     // 4 rows rg4..rg4+3
    int cg  = (tid & 7) * 4;                      // 4 cols cg..cg+3

    unsigned long long acc2[4][2];
    #pragma unroll
    for (int c4 = 0; c4 < 4; c4++) { acc2[c4][0] = 0ULL; acc2[c4][1] = 0ULL; }

    float4 pa0, pa1, pa2, pa3, pb;
    {
        const float* p = A + (size_t)(l0 + lrow) * LL + cseg;
        pa0 = *(const float4*)(p);      pa1 = *(const float4*)(p + 4);
        pa2 = *(const float4*)(p + 8);  pa3 = *(const float4*)(p + 12);
        pb  = *(const float4*)(Bb + (size_t)brow * DD + bcol);
    }

    for (int c = 0; c < 32; c++) {
        Ast[cseg+ 0][lrow]=pa0.x; Ast[cseg+ 1][lrow]=pa0.y;
        Ast[cseg+ 2][lrow]=pa0.z; Ast[cseg+ 3][lrow]=pa0.w;
        Ast[cseg+ 4][lrow]=pa1.x; Ast[cseg+ 5][lrow]=pa1.y;
        Ast[cseg+ 6][lrow]=pa1.z; Ast[cseg+ 7][lrow]=pa1.w;
        Ast[cseg+ 8][lrow]=pa2.x; Ast[cseg+ 9][lrow]=pa2.y;
        Ast[cseg+10][lrow]=pa2.z; Ast[cseg+11][lrow]=pa2.w;
        Ast[cseg+12][lrow]=pa3.x; Ast[cseg+13][lrow]=pa3.y;
        Ast[cseg+14][lrow]=pa3.z; Ast[cseg+15][lrow]=pa3.w;
        *(float4*)&Bs[brow][bcol] = pb;
        __syncthreads();

        if (c < 31) {
            int k0 = (c + 1) * 32;
            const float* p = A + (size_t)(l0 + lrow) * LL + k0 + cseg;
            pa0 = *(const float4*)(p);      pa1 = *(const float4*)(p + 4);
            pa2 = *(const float4*)(p + 8);  pa3 = *(const float4*)(p + 12);
            pb  = *(const float4*)(Bb + (size_t)(k0 + brow) * DD + bcol);
        }

        #pragma unroll
        for (int kk = 0; kk < 32; kk++) {
            ulonglong2 ap = *(const ulonglong2*)&Ast[kk][rg4];
            float4 bv = *(const float4*)&Bs[kk][cg];
            const float bl[4] = {bv.x, bv.y, bv.z, bv.w};
            #pragma unroll
            for (int c4 = 0; c4 < 4; c4++) {
                unsigned long long b2;
                DUP2(b2, bl[c4]);
                FMA2(acc2[c4][0], ap.x, b2);
                FMA2(acc2[c4][1], ap.y, b2);
            }
        }
        __syncthreads();
    }

    #pragma unroll
    for (int r = 0; r < 4; r++) {
        float4 o;
        #pragma unroll
        for (int c4 = 0; c4 < 4; c4++) {
            float lo, hi;
            UNPACK2(lo, hi, acc2[c4][r >> 1]);
            ((float*)&o)[c4] = (r & 1) ? hi : lo;
        }
        *(float4*)(Cb + (size_t)(l0 + rg4 + r) * c_row_stride + cg) = o;
    }
}

// ---------------------------------------------------------------------------
// K3a: S[bh][l][t] = leaky(ATT_SCALE * dot(q[bh][l], k[bh][t]))
// 64x64 tile, 4l x 4t per thread, packed FMA.
// ---------------------------------------------------------------------------
__global__ __launch_bounds__(256) void qk_gemm(
    const float* __restrict__ q, const float* __restrict__ k,
    float* __restrict__ S)
{
    __shared__ float Qt[32][68];   // [d][l]
    __shared__ float Kt[32][68];   // [d][t]

    int tid = threadIdx.x;
    int bh = blockIdx.z;
    int t0 = blockIdx.x * 64, l0 = blockIdx.y * 64;
    const float* qb = q + (size_t)bh * (LL * DD);
    const float* kb = k + (size_t)bh * (LL * DD);

    {
        int r = tid >> 3, c = (tid & 7) * 4;
        float4 v;
        v = *(const float4*)(qb + (size_t)(l0 + r) * DD + c);
        Qt[c+0][r] = v.x; Qt[c+1][r] = v.y; Qt[c+2][r] = v.z; Qt[c+3][r] = v.w;
        v = *(const float4*)(qb + (size_t)(l0 + r + 32) * DD + c);
        Qt[c+0][r+32] = v.x; Qt[c+1][r+32] = v.y; Qt[c+2][r+32] = v.z; Qt[c+3][r+32] = v.w;
        v = *(const float4*)(kb + (size_t)(t0 + r) * DD + c);
        Kt[c+0][r] = v.x; Kt[c+1][r] = v.y; Kt[c+2][r] = v.z; Kt[c+3][r] = v.w;
        v = *(const float4*)(kb + (size_t)(t0 + r + 32) * DD + c);
        Kt[c+0][r+32] = v.x; Kt[c+1][r+32] = v.y; Kt[c+2][r+32] = v.z; Kt[c+3][r+32] = v.w;
    }
    __syncthreads();

    int lg = (tid >> 4) * 4;   // 4 l rows
    int tg = (tid & 15) * 4;   // 4 t cols
    unsigned long long acc2[4][2];   // [t][l-pair]
    #pragma unroll
    for (int t = 0; t < 4; t++) { acc2[t][0] = 0ULL; acc2[t][1] = 0ULL; }

    #pragma unroll
    for (int d = 0; d < 32; d++) {
        ulonglong2 qp = *(const ulonglong2*)&Qt[d][lg];
        float4 kv = *(const float4*)&Kt[d][tg];
        const float kl[4] = {kv.x, kv.y, kv.z, kv.w};
        #pragma unroll
        for (int t = 0; t < 4; t++) {
            unsigned long long k2;
            DUP2(k2, kl[t]);
            FMA2(acc2[t][0], qp.x, k2);
            FMA2(acc2[t][1], qp.y, k2);
        }
    }

    float* Sb = S + (size_t)bh * (LL * LL);
    #pragma unroll
    for (int ll = 0; ll < 4; ll++) {
        float4 o;
        #pragma unroll
        for (int t = 0; t < 4; t++) {
            float lo, hi;
            UNPACK2(lo, hi, acc2[t][ll >> 1]);
            float val = ((ll & 1) ? hi : lo) * ATT_SCALE;
            ((float*)&o)[t] = (val > 0.f) ? val : 0.01f * val;
        }
        *(float4*)(Sb + (size_t)(l0 + lg + ll) * LL + t0 + tg) = o;
    }
}

// ---------------------------------------------------------------------------
// K3b (FUSED softmax): A[b,i,l,t] = softmax_t( mask( sum_h R[i,h]*S[b,h,l,t] ) )
// Block = (l, b): the whole row lives in the block's registers, so max, sum
// and normalized write all happen here. Masked entries -> exp(-inf) = exact 0.
// ---------------------------------------------------------------------------
__global__ __launch_bounds__(256) void mix_softmax_kernel(
    const float* __restrict__ S, const float* __restrict__ adj,
    const float* __restrict__ R, float* __restrict__ A_out)
{
    __shared__ float Rs[64];
    __shared__ float red[8][8];    // [warp][i]
    __shared__ float bc_mx[8];
    __shared__ float bc_ri[8];
    int tid = threadIdx.x, lane = tid & 31, w = tid >> 5;
    int l = blockIdx.x, b = blockIdx.y;
    if (tid < 64) Rs[tid] = R[tid];
    __syncthreads();

    int t4 = tid * 4;
    float4 s[8];
    #pragma unroll
    for (int h = 0; h < 8; h++)
        s[h] = *(const float4*)(S + ((size_t)((b * 8 + h) * LL + l)) * LL + t4);

    float4 o[8];
    float rmax[8];
    #pragma unroll
    for (int i = 0; i < 8; i++) {
        float mx = 0.f, my = 0.f, mz = 0.f, mw = 0.f;
        #pragma unroll
        for (int h = 0; h < 8; h++) {
            float r = Rs[i * 8 + h];
            mx += r * s[h].x; my += r * s[h].y;
            mz += r * s[h].z; mw += r * s[h].w;
        }
        size_t idx = ((size_t)((b * 8 + i) * LL + l)) * LL + t4;
        float4 a = *(const float4*)(adj + idx);
        o[i].x = (a.x > 0.f) ? mx : -INFINITY;
        o[i].y = (a.y > 0.f) ? my : -INFINITY;
        o[i].z = (a.z > 0.f) ? mz : -INFINITY;
        o[i].w = (a.w > 0.f) ? mw : -INFINITY;
        rmax[i] = fmaxf(fmaxf(o[i].x, o[i].y), fmaxf(o[i].z, o[i].w));
    }

    // block max per i
    #pragma unroll
    for (int i = 0; i < 8; i++) {
        float mx = rmax[i];
        #pragma unroll
        for (int off = 16; off; off >>= 1)
            mx = fmaxf(mx, __shfl_down_sync(0xffffffffu, mx, off));
        if (lane == 0) red[w][i] = mx;
    }
    __syncthreads();
    if (tid < 8) {
        float mx = red[0][tid];
        #pragma unroll
        for (int ww = 1; ww < 8; ww++) mx = fmaxf(mx, red[ww][tid]);
        bc_mx[tid] = mx;
    }
    __syncthreads();

    // exp + block sum per i
    float psum[8];
    #pragma unroll
    for (int i = 0; i < 8; i++) {
        float mx = bc_mx[i];
        o[i].x = __expf(o[i].x - mx);
        o[i].y = __expf(o[i].y - mx);
        o[i].z = __expf(o[i].z - mx);
        o[i].w = __expf(o[i].w - mx);
        psum[i] = (o[i].x + o[i].y) + (o[i].z + o[i].w);
    }
    __syncthreads();   // red[] reuse safe
    #pragma unroll
    for (int i = 0; i < 8; i++) {
        float sm = psum[i];
        #pragma unroll
        for (int off = 16; off; off >>= 1)
            sm += __shfl_down_sync(0xffffffffu, sm, off);
        if (lane == 0) red[w][i] = sm;
    }
    __syncthreads();
    if (tid < 8) {
        float sm = 0.f;
        #pragma unroll
        for (int ww = 0; ww < 8; ww++) sm += red[ww][tid];
        bc_ri[tid] = 1.f / sm;
    }
    __syncthreads();

    // normalize + write final A
    #pragma unroll
    for (int i = 0; i < 8; i++) {
        float ri = bc_ri[i];
        float4 a;
        a.x = o[i].x * ri; a.y = o[i].y * ri;
        a.z = o[i].z * ri; a.w = o[i].w * ri;
        *(float4*)(A_out + ((size_t)((b * 8 + i) * LL + l)) * LL + t4) = a;
    }
}

// ---------------------------------------------------------------------------
// K4: read-only column partials: pcol[seg][bi][t] = sum_{l in seg} exp(A[l,t])
// ---------------------------------------------------------------------------
__global__ __launch_bounds__(256) void colsum_kernel(
    const float* __restrict__ A, float* __restrict__ pcol)
{
    int bi = blockIdx.y;
    int seg = blockIdx.z;
    int t = blockIdx.x * 256 + threadIdx.x;
    const float* base = A + (size_t)bi * (LL * LL);

    int lr0 = seg * 256;
    float s0 = 0.f, s1 = 0.f, s2 = 0.f, s3 = 0.f;
    for (int lr = lr0; lr < lr0 + 256; lr += 4) {
        s0 += __expf(base[(size_t)(lr + 0) * LL + t]);
        s1 += __expf(base[(size_t)(lr + 1) * LL + t]);
        s2 += __expf(base[(size_t)(lr + 2) * LL + t]);
        s3 += __expf(base[(size_t)(lr + 3) * LL + t]);
    }
    pcol[(size_t)(seg * 32 + bi) * LL + t] = (s0 + s1) + (s2 + s3);
}

// ---------------------------------------------------------------------------
// K5: Ar[b,i,t,l] = exp(A[b,i,l,t]) / colsum(t)  (tiled transpose; 4 partials)
// ---------------------------------------------------------------------------
__global__ __launch_bounds__(256) void transpose_exp_kernel(
    const float* __restrict__ A, const float* __restrict__ pcol,
    float* __restrict__ Ar)
{
    __shared__ float Ts[32][33];
    int bi = blockIdx.z;
    int l0 = blockIdx.x * 32, t0 = blockIdx.y * 32;
    int lane = threadIdx.x & 31, wr = threadIdx.x >> 5;
    const float* base = A + (size_t)bi * (LL * LL);
    float* obase = Ar + (size_t)bi * (LL * LL);
    #pragma unroll
    for (int j = 0; j < 4; j++) {
        int lr = wr + j * 8;
        Ts[lr][lane] = base[(size_t)(l0 + lr) * LL + t0 + lane];
    }
    __syncthreads();
    #pragma unroll
    for (int j = 0; j < 4; j++) {
        int tr = wr + j * 8;
        int tt = t0 + tr;
        float rc = 1.f / (pcol[(size_t)(0 * 32 + bi) * LL + tt]
                        + pcol[(size_t)(1 * 32 + bi) * LL + tt]
                        + pcol[(size_t)(2 * 32 + bi) * LL + tt]
                        + pcol[(size_t)(3 * 32 + bi) * LL + tt]);
        obase[(size_t)tt * LL + l0 + lane] = __expf(Ts[lane][tr]) * rc;
    }
}

// ---------------------------------------------------------------------------
// K6: Out[r,n] = sum_m gelu(Vm[r,m]) * Wp[m,n]. 128x32 tile, 4x4 thread tile.
// ---------------------------------------------------------------------------
__device__ __forceinline__ float gelu_exact(float v)
{
    return 0.5f * v * (1.f + erff(v * 0.70710678118654752f));
}

__global__ __launch_bounds__(256) void out_gemm(
    const float* __restrict__ V0, const float* __restrict__ V1,
    const float* __restrict__ Wp,
    float* __restrict__ O0, float* __restrict__ O1)
{
    __shared__ float Gs[32][132];   // [k][row], gelu'd
    __shared__ float Ws[32][32];    // [k][n]
    const float* Vm = blockIdx.z ? V1 : V0;
    float* Out = blockIdx.z ? O1 : O0;
    int tid = threadIdx.x;
    int r0 = blockIdx.x * 128, n0 = blockIdx.y * 32;

    int lrow = tid >> 1, cseg = (tid & 1) * 16;
    int brow = tid >> 3, bcol = (tid & 7) * 4;
    int rg4 = (tid >> 3) * 4;
    int cg  = (tid & 7) * 4;

    unsigned long long acc2[4][2];
    #pragma unroll
    for (int c4 = 0; c4 < 4; c4++) { acc2[c4][0] = 0ULL; acc2[c4][1] = 0ULL; }

    for (int k0 = 0; k0 < DIMM; k0 += 32) {
        const float* vrow = Vm + (size_t)(r0 + lrow) * DIMM + k0 + cseg;
        float4 a0 = *(const float4*)(vrow);
        float4 a1 = *(const float4*)(vrow + 4);
        float4 a2 = *(const float4*)(vrow + 8);
        float4 a3 = *(const float4*)(vrow + 12);
        Gs[cseg+ 0][lrow]=gelu_exact(a0.x); Gs[cseg+ 1][lrow]=gelu_exact(a0.y);
        Gs[cseg+ 2][lrow]=gelu_exact(a0.z); Gs[cseg+ 3][lrow]=gelu_exact(a0.w);
        Gs[cseg+ 4][lrow]=gelu_exact(a1.x); Gs[cseg+ 5][lrow]=gelu_exact(a1.y);
        Gs[cseg+ 6][lrow]=gelu_exact(a1.z); Gs[cseg+ 7][lrow]=gelu_exact(a1.w);
        Gs[cseg+ 8][lrow]=gelu_exact(a2.x); Gs[cseg+ 9][lrow]=gelu_exact(a2.y);
        Gs[cseg+10][lrow]=gelu_exact(a2.z); Gs[cseg+11][lrow]=gelu_exact(a2.w);
        Gs[cseg+12][lrow]=gelu_exact(a3.x); Gs[cseg+13][lrow]=gelu_exact(a3.y);
        Gs[cseg+14][lrow]=gelu_exact(a3.z); Gs[cseg+15][lrow]=gelu_exact(a3.w);
        *(float4*)&Ws[brow][bcol] =
            *(const float4*)(Wp + (size_t)(k0 + brow) * DIMM + n0 + bcol);
        __syncthreads();

        #pragma unroll
        for (int kk = 0; kk < 32; kk++) {
            ulonglong2 ap = *(const ulonglong2*)&Gs[kk][rg4];
            float4 bv = *(const float4*)&Ws[kk][cg];
            const float bl[4] = {bv.x, bv.y, bv.z, bv.w};
            #pragma unroll
            for (int c4 = 0; c4 < 4; c4++) {
                unsigned long long b2;
                DUP2(b2, bl[c4]);
                FMA2(acc2[c4][0], ap.x, b2);
                FMA2(acc2[c4][1], ap.y, b2);
            }
        }
        __syncthreads();
    }

    #pragma unroll
    for (int r = 0; r < 4; r++) {
        float4 o;
        #pragma unroll
        for (int c4 = 0; c4 < 4; c4++) {
            float lo, hi;
            UNPACK2(lo, hi, acc2[c4][r >> 1]);
            ((float*)&o)[c4] = (r & 1) ? hi : lo;
        }
        *(float4*)(Out + (size_t)(r0 + rg4 + r) * DIMM + n0 + cg) = o;
    }
}

// ---------------------------------------------------------------------------
// Launch. Output layout (float32, reference return order):
//   out [4,1024,256] | out_resize [4,1024,256] | A [4,8,1024,1024] | Ar [...]
// S (QK^T logits) borrows the Ar region until transpose overwrites it.
// ---------------------------------------------------------------------------
extern "C" void kernel_launch(void* const* d_in, const int* in_sizes, int n_in,
                              void* d_out, int out_size)
{
    const float* x    = (const float*)d_in[0];
    const float* rx   = (const float*)d_in[1];
    const float* adj  = (const float*)d_in[2];
    const float* adjr = (const float*)d_in[3];
    const float* Wq   = (const float*)d_in[4];
    const float* Wk   = (const float*)d_in[5];
    const float* Wv   = (const float*)d_in[6];
    const float* R    = (const float*)d_in[7];
    const float* Wp   = (const float*)d_in[8];

    float* out  = (float*)d_out;
    float* outr = out + (size_t)BB * LL * DIMM;
    float* A    = out + (size_t)2 * BB * LL * DIMM;
    float* Ar   = A + (size_t)BB * HH * LL * LL;

    float* s = nullptr;
    cudaGetSymbolAddress((void**)&s, g_scratch);

    // K1: projections (xq, xk, xv, rv)
    proj_kernel<<<dim3(4096, 4), 256>>>(x, rx, Wq, Wk, Wv, s);

    // K2: q = adj @ xq ; k = adjr @ xk  -- sparse binary gather (exact)
    spmm_binary<<<dim3(128, 32, 2), 256>>>(adj,  s + OFF_XQ, s + OFF_Q,
                                           adjr, s + OFF_XK, s + OFF_K);

    // K3a: S = leaky(scale * q @ k^T)  -> Ar region (scratch use)
    qk_gemm<<<dim3(16, 16, 32), 256>>>(s + OFF_Q, s + OFF_K, Ar);

    // K3b: R-mix + mask + FULL row softmax -> final A
    mix_softmax_kernel<<<dim3(1024, 4), 256>>>(Ar, adj, R, A);

    // K4: read-only column partials (4 segments)
    colsum_kernel<<<dim3(4, 32, 4), 256>>>(A, s + OFF_PCOL);

    // K5: dual softmax on transpose -> Ar (overwrites S scratch)
    transpose_exp_kernel<<<dim3(32, 32, 32), 256>>>(A, s + OFF_PCOL, Ar);

    // v = A @ xv  -- sparse weighted gather
    spmm_weighted<<<dim3(128, 32), 256>>>(A, s + OFF_XV, s + OFF_VM);

    // vr = Ar @ rv -- dense
    gemm_dense<<<dim3(8, 32), 256>>>(Ar, s + OFF_RV, s + OFF_VRM,
                                     (size_t)LL * DIMM, (size_t)DD, DIMM);

    // K6: out = gelu(v) @ Wp ; out_resize = gelu(vr) @ Wp
    out_gemm<<<dim3(32, 8, 2), 256>>>(s + OFF_VM, s + OFF_VRM, Wp, out, outr);
}

// round 12
// speedup vs baseline: 1.6000x; 1.0585x over previous
#include <cuda_runtime.h>
#include <math.h>

#define BB 4
#define HH 8
#define LL 1024
#define DD 32
#define DIMM 256
#define ATT_SCALE 0.0625f   // DIM^-0.5 = 1/16

#define M1 1048576
// scratch layout (floats)
#define OFF_XQ   (0*M1)
#define OFF_XK   (1*M1)
#define OFF_XV   (2*M1)
#define OFF_RV   (3*M1)
#define OFF_Q    (4*M1)
#define OFF_K    (5*M1)
#define OFF_VM   (6*M1)
#define OFF_VRA  (7*M1)
#define OFF_VRB  (8*M1)
#define OFF_PCOL  (9*M1)                    // 4 segs x 32 bi x 1024 t
#define OFF_RCINV (9*M1 + 131072)           // 32 bi x 1024 t

__device__ float g_scratch[9*M1 + 163840];

// packed fp32x2 helpers (sm_100+)
#define FMA2(acc, a, b) \
    asm("fma.rn.f32x2 %0, %1, %2, %0;" : "+l"(acc) : "l"(a), "l"(b))
#define DUP2(dst, v) \
    asm("mov.b64 %0, {%1, %1};" : "=l"(dst) : "f"(v))
#define UNPACK2(lo, hi, v) \
    asm("mov.b64 {%0, %1}, %2;" : "=f"(lo), "=f"(hi) : "l"(v))

// ---------------------------------------------------------------------------
// K1: per-head projections  dst[b,h,t,d] = sum_dp src[b,t,h*32+dp] * W[dp,d]
// ---------------------------------------------------------------------------
__global__ __launch_bounds__(256) void proj_kernel(
    const float* __restrict__ x, const float* __restrict__ rx,
    const float* __restrict__ Wq, const float* __restrict__ Wk,
    const float* __restrict__ Wv, float* __restrict__ scratch)
{
    int tid = threadIdx.x;
    int which = blockIdx.y;
    const float* src = (which == 0 || which == 2) ? x : rx;
    const float* W = (which == 0) ? Wq : ((which == 1) ? Wk : Wv);
    float* dst = scratch + (size_t)which * M1;

    __shared__ float Ws[1024];
    __shared__ float Xs[8][32];
    for (int i = tid; i < 1024; i += 256) Ws[i] = W[i];

    int r = blockIdx.x * 8 + (tid >> 5);   // r = (b*8+h)*1024 + t
    int d = tid & 31;
    int b = r >> 13;
    int h = (r >> 10) & 7;
    int t = r & 1023;
    Xs[tid >> 5][d] = src[((size_t)(b * LL + t)) * DIMM + h * 32 + d];
    __syncthreads();

    float acc = 0.f;
    #pragma unroll
    for (int dp = 0; dp < 32; dp++) acc += Xs[tid >> 5][dp] * Ws[dp * 32 + d];
    dst[(size_t)r * 32 + d] = acc;
}

// ---------------------------------------------------------------------------
// K2: SPARSE binary gather-sum:  O[bh][l][d] = sum_{t: G[bh][l][t] > 0} X[bh][t][d]
// ---------------------------------------------------------------------------
__global__ __launch_bounds__(256) void spmm_binary(
    const float* __restrict__ G0, const float* __restrict__ X0, float* __restrict__ O0,
    const float* __restrict__ G1, const float* __restrict__ X1, float* __restrict__ O1)
{
    int lane = threadIdx.x & 31, w = threadIdx.x >> 5;
    int l = blockIdx.x * 8 + w;
    int bh = blockIdx.y;
    const float* G = (blockIdx.z ? G1 : G0) + (size_t)bh * (LL * LL) + (size_t)l * LL;
    const float* X = (blockIdx.z ? X1 : X0) + (size_t)bh * (LL * DD);
    float* O = (blockIdx.z ? O1 : O0) + (size_t)bh * (LL * DD);

    float acc0 = 0.f, acc1 = 0.f;
    for (int t0 = 0; t0 < LL; t0 += 128) {
        float4 g = *(const float4*)&G[t0 + lane * 4];
        #pragma unroll
        for (int c = 0; c < 4; c++) {
            float gv = (c == 0) ? g.x : (c == 1) ? g.y : (c == 2) ? g.z : g.w;
            unsigned m = __ballot_sync(0xffffffffu, gv > 0.f);
            while (m) {
                int j = __ffs(m) - 1; m &= m - 1;
                acc0 += X[(t0 + j * 4 + c) * DD + lane];
                if (m) {
                    j = __ffs(m) - 1; m &= m - 1;
                    acc1 += X[(t0 + j * 4 + c) * DD + lane];
                }
            }
        }
    }
    O[(size_t)l * DD + lane] = acc0 + acc1;
}

// ---------------------------------------------------------------------------
// K2b: SPARSE weighted gather:  VM[b,l,h*32+d] = sum_{t: A[bh][l][t] > 0} A*X
// ---------------------------------------------------------------------------
__global__ __launch_bounds__(256) void spmm_weighted(
    const float* __restrict__ A, const float* __restrict__ X, float* __restrict__ O)
{
    int lane = threadIdx.x & 31, w = threadIdx.x >> 5;
    int l = blockIdx.x * 8 + w;
    int bh = blockIdx.y;
    int b = bh >> 3, h = bh & 7;
    const float* G = A + (size_t)bh * (LL * LL) + (size_t)l * LL;
    const float* Xb = X + (size_t)bh * (LL * DD);

    float acc0 = 0.f, acc1 = 0.f;
    for (int t0 = 0; t0 < LL; t0 += 128) {
        float4 g = *(const float4*)&G[t0 + lane * 4];
        #pragma unroll
        for (int c = 0; c < 4; c++) {
            float gv = (c == 0) ? g.x : (c == 1) ? g.y : (c == 2) ? g.z : g.w;
            unsigned m = __ballot_sync(0xffffffffu, gv > 0.f);
            while (m) {
                int j = __ffs(m) - 1; m &= m - 1;
                float av = __shfl_sync(0xffffffffu, gv, j);
                acc0 += av * Xb[(t0 + j * 4 + c) * DD + lane];
                if (m) {
                    j = __ffs(m) - 1; m &= m - 1;
                    float av2 = __shfl_sync(0xffffffffu, gv, j);
                    acc1 += av2 * Xb[(t0 + j * 4 + c) * DD + lane];
                }
            }
        }
    }
    O[(size_t)b * (LL * DIMM) + (size_t)l * DIMM + h * 32 + lane] = acc0 + acc1;
}

// ---------------------------------------------------------------------------
// K3a: S[bh][l][t] = leaky(ATT_SCALE * dot(q[bh][l], k[bh][t]))
// 128x64 tile, 8l x 4t per thread (1.5 B smem / MAC), packed FMA.
// ---------------------------------------------------------------------------
__global__ __launch_bounds__(256) void qk_gemm(
    const float* __restrict__ q, const float* __restrict__ k,
    float* __restrict__ S)
{
    __shared__ float Qt[32][132];   // [d][l]
    __shared__ float Kt[32][68];    // [d][t]

    int tid = threadIdx.x;
    int bh = blockIdx.z;
    int t0 = blockIdx.x * 64, l0 = blockIdx.y * 128;
    const float* qb = q + (size_t)bh * (LL * DD);
    const float* kb = k + (size_t)bh * (LL * DD);

    // stage Q (128 rows x 32 d) transposed
    {
        int r = tid >> 1, cs = (tid & 1) * 16;
        #pragma unroll
        for (int j = 0; j < 4; j++) {
            float4 v = *(const float4*)(qb + (size_t)(l0 + r) * DD + cs + j * 4);
            Qt[cs + j*4 + 0][r] = v.x; Qt[cs + j*4 + 1][r] = v.y;
            Qt[cs + j*4 + 2][r] = v.z; Qt[cs + j*4 + 3][r] = v.w;
        }
    }
    // stage K (64 rows x 32 d) transposed
    {
        int r2 = tid & 63, cs2 = (tid >> 6) * 8;
        #pragma unroll
        for (int j = 0; j < 2; j++) {
            float4 v = *(const float4*)(kb + (size_t)(t0 + r2) * DD + cs2 + j * 4);
            Kt[cs2 + j*4 + 0][r2] = v.x; Kt[cs2 + j*4 + 1][r2] = v.y;
            Kt[cs2 + j*4 + 2][r2] = v.z; Kt[cs2 + j*4 + 3][r2] = v.w;
        }
    }
    __syncthreads();

    int lg = (tid >> 4) * 8;   // 8 l rows
    int tg = (tid & 15) * 4;   // 4 t cols
    unsigned long long acc2[4][4];   // [t][l-pair]
    #pragma unroll
    for (int t = 0; t < 4; t++)
        #pragma unroll
        for (int p = 0; p < 4; p++) acc2[t][p] = 0ULL;

    #pragma unroll
    for (int d = 0; d < 32; d++) {
        ulonglong2 q0 = *(const ulonglong2*)&Qt[d][lg];
        ulonglong2 q1 = *(const ulonglong2*)&Qt[d][lg + 4];
        float4 kv = *(const float4*)&Kt[d][tg];
        const float kl[4] = {kv.x, kv.y, kv.z, kv.w};
        #pragma unroll
        for (int t = 0; t < 4; t++) {
            unsigned long long k2;
            DUP2(k2, kl[t]);
            FMA2(acc2[t][0], q0.x, k2);
            FMA2(acc2[t][1], q0.y, k2);
            FMA2(acc2[t][2], q1.x, k2);
            FMA2(acc2[t][3], q1.y, k2);
        }
    }

    float* Sb = S + (size_t)bh * (LL * LL);
    #pragma unroll
    for (int r = 0; r < 8; r++) {
        float4 o;
        #pragma unroll
        for (int t = 0; t < 4; t++) {
            float lo, hi;
            UNPACK2(lo, hi, acc2[t][r >> 1]);
            float val = ((r & 1) ? hi : lo) * ATT_SCALE;
            ((float*)&o)[t] = (val > 0.f) ? val : 0.01f * val;
        }
        *(float4*)(Sb + (size_t)(l0 + lg + r) * LL + t0 + tg) = o;
    }
}

// ---------------------------------------------------------------------------
// K3b (FUSED softmax): A[b,i,l,t] = softmax_t( mask( sum_h R[i,h]*S[b,h,l,t] ) )
// ---------------------------------------------------------------------------
__global__ __launch_bounds__(256) void mix_softmax_kernel(
    const float* __restrict__ S, const float* __restrict__ adj,
    const float* __restrict__ R, float* __restrict__ A_out)
{
    __shared__ float Rs[64];
    __shared__ float red[8][8];    // [warp][i]
    __shared__ float bc_mx[8];
    __shared__ float bc_ri[8];
    int tid = threadIdx.x, lane = tid & 31, w = tid >> 5;
    int l = blockIdx.x, b = blockIdx.y;
    if (tid < 64) Rs[tid] = R[tid];
    __syncthreads();

    int t4 = tid * 4;
    float4 s[8];
    #pragma unroll
    for (int h = 0; h < 8; h++)
        s[h] = *(const float4*)(S + ((size_t)((b * 8 + h) * LL + l)) * LL + t4);

    float4 o[8];
    float rmax[8];
    #pragma unroll
    for (int i = 0; i < 8; i++) {
        float mx = 0.f, my = 0.f, mz = 0.f, mw = 0.f;
        #pragma unroll
        for (int h = 0; h < 8; h++) {
            float r = Rs[i * 8 + h];
            mx += r * s[h].x; my += r * s[h].y;
            mz += r * s[h].z; mw += r * s[h].w;
        }
        size_t idx = ((size_t)((b * 8 + i) * LL + l)) * LL + t4;
        float4 a = *(const float4*)(adj + idx);
        o[i].x = (a.x > 0.f) ? mx : -INFINITY;
        o[i].y = (a.y > 0.f) ? my : -INFINITY;
        o[i].z = (a.z > 0.f) ? mz : -INFINITY;
        o[i].w = (a.w > 0.f) ? mw : -INFINITY;
        rmax[i] = fmaxf(fmaxf(o[i].x, o[i].y), fmaxf(o[i].z, o[i].w));
    }

    #pragma unroll
    for (int i = 0; i < 8; i++) {
        float mx = rmax[i];
        #pragma unroll
        for (int off = 16; off; off >>= 1)
            mx = fmaxf(mx, __shfl_down_sync(0xffffffffu, mx, off));
        if (lane == 0) red[w][i] = mx;
    }
    __syncthreads();
    if (tid < 8) {
        float mx = red[0][tid];
        #pragma unroll
        for (int ww = 1; ww < 8; ww++) mx = fmaxf(mx, red[ww][tid]);
        bc_mx[tid] = mx;
    }
    __syncthreads();

    float psum[8];
    #pragma unroll
    for (int i = 0; i < 8; i++) {
        float mx = bc_mx[i];
        o[i].x = __expf(o[i].x - mx);
        o[i].y = __expf(o[i].y - mx);
        o[i].z = __expf(o[i].z - mx);
        o[i].w = __expf(o[i].w - mx);
        psum[i] = (o[i].x + o[i].y) + (o[i].z + o[i].w);
    }
    __syncthreads();
    #pragma unroll
    for (int i = 0; i < 8; i++) {
        float sm = psum[i];
        #pragma unroll
        for (int off = 16; off; off >>= 1)
            sm += __shfl_down_sync(0xffffffffu, sm, off);
        if (lane == 0) red[w][i] = sm;
    }
    __syncthreads();
    if (tid < 8) {
        float sm = 0.f;
        #pragma unroll
        for (int ww = 0; ww < 8; ww++) sm += red[ww][tid];
        bc_ri[tid] = 1.f / sm;
    }
    __syncthreads();

    #pragma unroll
    for (int i = 0; i < 8; i++) {
        float ri = bc_ri[i];
        float4 a;
        a.x = o[i].x * ri; a.y = o[i].y * ri;
        a.z = o[i].z * ri; a.w = o[i].w * ri;
        *(float4*)(A_out + ((size_t)((b * 8 + i) * LL + l)) * LL + t4) = a;
    }
}

// ---------------------------------------------------------------------------
// K4: column partials: pcol[seg][bi][t] = sum_{l in seg} exp(A[l,t])
// ---------------------------------------------------------------------------
__global__ __launch_bounds__(256) void colsum_kernel(
    const float* __restrict__ A, float* __restrict__ pcol)
{
    int bi = blockIdx.y;
    int seg = blockIdx.z;
    int t = blockIdx.x * 256 + threadIdx.x;
    const float* base = A + (size_t)bi * (LL * LL);

    int lr0 = seg * 256;
    float s0 = 0.f, s1 = 0.f, s2 = 0.f, s3 = 0.f;
    for (int lr = lr0; lr < lr0 + 256; lr += 4) {
        s0 += __expf(base[(size_t)(lr + 0) * LL + t]);
        s1 += __expf(base[(size_t)(lr + 1) * LL + t]);
        s2 += __expf(base[(size_t)(lr + 2) * LL + t]);
        s3 += __expf(base[(size_t)(lr + 3) * LL + t]);
    }
    pcol[(size_t)(seg * 32 + bi) * LL + t] = (s0 + s1) + (s2 + s3);
}

// ---------------------------------------------------------------------------
// K4b: rcinv[bi][t] = 1 / (sum of 4 partials)   (same order as before)
// ---------------------------------------------------------------------------
__global__ __launch_bounds__(256) void rc_combine_kernel(
    const float* __restrict__ pcol, float* __restrict__ rcinv)
{
    int i = blockIdx.x * 256 + threadIdx.x;   // 32768
    int bi = i >> 10, t = i & 1023;
    rcinv[i] = 1.f / (pcol[(size_t)(0 * 32 + bi) * LL + t]
                    + pcol[(size_t)(1 * 32 + bi) * LL + t]
                    + pcol[(size_t)(2 * 32 + bi) * LL + t]
                    + pcol[(size_t)(3 * 32 + bi) * LL + t]);
}

// ---------------------------------------------------------------------------
// K5 (FUSED): Ar tile construction + write + GEMM, per (b,h), k-split z.
//   Ar[t,l] = exp(A[l,t]) * rcinv[t]   (written to ArOut, each element once)
//   Cpart[z][b][t][h*32+n] = sum_{l in z-half} Ar[t,l] * rv[l,n]
// 128 t-rows x 32 n tile; 4x4 thread tile; Ast staged as [l][t].
// ---------------------------------------------------------------------------
__global__ __launch_bounds__(256) void gemm_ar(
    const float* __restrict__ A, const float* __restrict__ rcinv,
    const float* __restrict__ Bm, float* __restrict__ ArOut,
    float* __restrict__ Cp0, float* __restrict__ Cp1)
{
    __shared__ float Ast[32][132];   // [l][t] holding Ar values
    __shared__ float Bs[32][32];     // [l][n]

    int tid = threadIdx.x;
    int bh = blockIdx.y;
    int kz = blockIdx.z;
    int t0 = blockIdx.x * 128;
    const float* Ab  = A + (size_t)bh * (LL * LL);
    const float* Bb  = Bm + (size_t)bh * (LL * DD);
    const float* rcb = rcinv + bh * LL;
    float* Arb = ArOut + (size_t)bh * (LL * LL);
    float* C = (kz ? Cp1 : Cp0) + (size_t)(bh >> 3) * (LL * DIMM);
    int hh = bh & 7;

    int lr = tid >> 3, tseg = (tid & 7) * 16;   // A staging
    int brow = tid >> 3, bcol = (tid & 7) * 4;  // B staging
    int rg4 = (tid >> 3) * 4, cg = (tid & 7) * 4;

    unsigned long long acc2[4][2];
    #pragma unroll
    for (int c4 = 0; c4 < 4; c4++) { acc2[c4][0] = 0ULL; acc2[c4][1] = 0ULL; }

    for (int c = 0; c < 16; c++) {
        int l0 = kz * 512 + c * 32;
        // stage Ar values (coalesced A read; conflict-free f4 smem stores)
        #pragma unroll
        for (int j = 0; j < 4; j++) {
            float4 v  = *(const float4*)(Ab + (size_t)(l0 + lr) * LL + t0 + tseg + j * 4);
            float4 rc = *(const float4*)(rcb + t0 + tseg + j * 4);
            float4 ar;
            ar.x = __expf(v.x) * rc.x; ar.y = __expf(v.y) * rc.y;
            ar.z = __expf(v.z) * rc.z; ar.w = __expf(v.w) * rc.w;
            *(float4*)&Ast[lr][tseg + j * 4] = ar;
        }
        *(float4*)&Bs[brow][bcol] =
            *(const float4*)(Bb + (size_t)(l0 + brow) * DD + bcol);
        __syncthreads();

        // write Ar tile to gmem (coalesced rows; modest smem conflicts)
        #pragma unroll
        for (int p = 0; p < 4; p++) {
            int tr = p * 32 + (tid >> 3);
            int lc = (tid & 7) * 4;
            float4 wv;
            wv.x = Ast[lc + 0][tr]; wv.y = Ast[lc + 1][tr];
            wv.z = Ast[lc + 2][tr]; wv.w = Ast[lc + 3][tr];
            *(float4*)(Arb + (size_t)(t0 + tr) * LL + l0 + lc) = wv;
        }

        // GEMM: C[t][n] += Ar[t][l] * B[l][n]
        #pragma unroll
        for (int kk = 0; kk < 32; kk++) {
            ulonglong2 ap = *(const ulonglong2*)&Ast[kk][rg4];
            float4 bv = *(const float4*)&Bs[kk][cg];
            const float bl[4] = {bv.x, bv.y, bv.z, bv.w};
            #pragma unroll
            for (int c4 = 0; c4 < 4; c4++) {
                unsigned long long b2;
                DUP2(b2, bl[c4]);
                FMA2(acc2[c4][0], ap.x, b2);
                FMA2(acc2[c4][1], ap.y, b2);
            }
        }
        __syncthreads();
    }

    #pragma unroll
    for (int r = 0; r < 4; r++) {
        float4 o;
        #pragma unroll
        for (int c4 = 0; c4 < 4; c4++) {
            float lo, hi;
            UNPACK2(lo, hi, acc2[c4][r >> 1]);
            ((float*)&o)[c4] = (r & 1) ? hi : lo;
        }
        *(float4*)(C + (size_t)(t0 + rg4 + r) * DIMM + hh * 32 + cg) = o;
    }
}

// ---------------------------------------------------------------------------
// K6: Out[r,n] = sum_m gelu(Vm[r,m]) * Wp[m,n]. 128x32 tile, 4x4 thread tile.
// z=0: Vm = V0. z=1: Vm = V1a + V1b (k-split partials summed pre-gelu).
// ---------------------------------------------------------------------------
__device__ __forceinline__ float gelu_exact(float v)
{
    return 0.5f * v * (1.f + erff(v * 0.70710678118654752f));
}

__global__ __launch_bounds__(256) void out_gemm(
    const float* __restrict__ V0, const float* __restrict__ V1a,
    const float* __restrict__ V1b, const float* __restrict__ Wp,
    float* __restrict__ O0, float* __restrict__ O1)
{
    __shared__ float Gs[32][132];   // [k][row], gelu'd
    __shared__ float Ws[32][32];    // [k][n]
    int z = blockIdx.z;
    float* Out = z ? O1 : O0;
    int tid = threadIdx.x;
    int r0 = blockIdx.x * 128, n0 = blockIdx.y * 32;

    int lrow = tid >> 1, cseg = (tid & 1) * 16;
    int brow = tid >> 3, bcol = (tid & 7) * 4;
    int rg4 = (tid >> 3) * 4;
    int cg  = (tid & 7) * 4;

    unsigned long long acc2[4][2];
    #pragma unroll
    for (int c4 = 0; c4 < 4; c4++) { acc2[c4][0] = 0ULL; acc2[c4][1] = 0ULL; }

    for (int k0 = 0; k0 < DIMM; k0 += 32) {
        size_t roff = (size_t)(r0 + lrow) * DIMM + k0 + cseg;
        #pragma unroll
        for (int j = 0; j < 4; j++) {
            float4 a;
            if (z) {
                float4 p0 = *(const float4*)(V1a + roff + j * 4);
                float4 p1 = *(const float4*)(V1b + roff + j * 4);
                a.x = p0.x + p1.x; a.y = p0.y + p1.y;
                a.z = p0.z + p1.z; a.w = p0.w + p1.w;
            } else {
                a = *(const float4*)(V0 + roff + j * 4);
            }
            Gs[cseg + j*4 + 0][lrow] = gelu_exact(a.x);
            Gs[cseg + j*4 + 1][lrow] = gelu_exact(a.y);
            Gs[cseg + j*4 + 2][lrow] = gelu_exact(a.z);
            Gs[cseg + j*4 + 3][lrow] = gelu_exact(a.w);
        }
        *(float4*)&Ws[brow][bcol] =
            *(const float4*)(Wp + (size_t)(k0 + brow) * DIMM + n0 + bcol);
        __syncthreads();

        #pragma unroll
        for (int kk = 0; kk < 32; kk++) {
            ulonglong2 ap = *(const ulonglong2*)&Gs[kk][rg4];
            float4 bv = *(const float4*)&Ws[kk][cg];
            const float bl[4] = {bv.x, bv.y, bv.z, bv.w};
            #pragma unroll
            for (int c4 = 0; c4 < 4; c4++) {
                unsigned long long b2;
                DUP2(b2, bl[c4]);
                FMA2(acc2[c4][0], ap.x, b2);
                FMA2(acc2[c4][1], ap.y, b2);
            }
        }
        __syncthreads();
    }

    #pragma unroll
    for (int r = 0; r < 4; r++) {
        float4 o;
        #pragma unroll
        for (int c4 = 0; c4 < 4; c4++) {
            float lo, hi;
            UNPACK2(lo, hi, acc2[c4][r >> 1]);
            ((float*)&o)[c4] = (r & 1) ? hi : lo;
        }
        *(float4*)(Out + (size_t)(r0 + rg4 + r) * DIMM + n0 + cg) = o;
    }
}

// ---------------------------------------------------------------------------
// Launch. Output layout (float32, reference return order):
//   out [4,1024,256] | out_resize [4,1024,256] | A [4,8,1024,1024] | Ar [...]
// S (QK^T logits) borrows the Ar region until gemm_ar overwrites it.
// ---------------------------------------------------------------------------
extern "C" void kernel_launch(void* const* d_in, const int* in_sizes, int n_in,
                              void* d_out, int out_size)
{
    const float* x    = (const float*)d_in[0];
    const float* rx   = (const float*)d_in[1];
    const float* adj  = (const float*)d_in[2];
    const float* adjr = (const float*)d_in[3];
    const float* Wq   = (const float*)d_in[4];
    const float* Wk   = (const float*)d_in[5];
    const float* Wv   = (const float*)d_in[6];
    const float* R    = (const float*)d_in[7];
    const float* Wp   = (const float*)d_in[8];

    float* out  = (float*)d_out;
    float* outr = out + (size_t)BB * LL * DIMM;
    float* A    = out + (size_t)2 * BB * LL * DIMM;
    float* Ar   = A + (size_t)BB * HH * LL * LL;

    float* s = nullptr;
    cudaGetSymbolAddress((void**)&s, g_scratch);

    // K1: projections (xq, xk, xv, rv)
    proj_kernel<<<dim3(4096, 4), 256>>>(x, rx, Wq, Wk, Wv, s);

    // K2: q = adj @ xq ; k = adjr @ xk  -- sparse binary gather (exact)
    spmm_binary<<<dim3(128, 32, 2), 256>>>(adj,  s + OFF_XQ, s + OFF_Q,
                                           adjr, s + OFF_XK, s + OFF_K);

    // K3a: S = leaky(scale * q @ k^T)  -> Ar region (scratch use)
    qk_gemm<<<dim3(16, 8, 32), 256>>>(s + OFF_Q, s + OFF_K, Ar);

    // K3b: R-mix + mask + full row softmax -> final A
    mix_softmax_kernel<<<dim3(1024, 4), 256>>>(Ar, adj, R, A);

    // K4: column partials + combine
    colsum_kernel<<<dim3(4, 32, 4), 256>>>(A, s + OFF_PCOL);
    rc_combine_kernel<<<128, 256>>>(s + OFF_PCOL, s + OFF_RCINV);

    // v = A @ xv  -- sparse weighted gather
    spmm_weighted<<<dim3(128, 32), 256>>>(A, s + OFF_XV, s + OFF_VM);

    // K5: fused Ar construction + write + vr GEMM (k-split partials)
    gemm_ar<<<dim3(8, 32, 2), 256>>>(A, s + OFF_RCINV, s + OFF_RV, Ar,
                                     s + OFF_VRA, s + OFF_VRB);

    // K6: out = gelu(v) @ Wp ; out_resize = gelu(vra+vrb) @ Wp
    out_gemm<<<dim3(32, 8, 2), 256>>>(s + OFF_VM, s + OFF_VRA, s + OFF_VRB,
                                      Wp, out, outr);
}